// round 3
// baseline (speedup 1.0000x reference)
#include <cuda_runtime.h>
#include <math.h>

#define NN 20000
#define EE 320000
#define DD 256
#define HH 2
#define CC 128
#define EDIM 73
#define LL 3

// ---------------- scratch (static __device__, no allocation) ----------------
__device__ float g_edge_attr[EE * EDIM];   // 93 MB
__device__ float g_h[NN * DD];
__device__ float g_q[NN * DD];
__device__ float g_k[NN * DD];
__device__ float g_v[NN * DD];
__device__ float g_skip[NN * DD];
__device__ float g_e[EE * DD];             // 328 MB
__device__ float g_aggr[NN * DD];
__device__ int   g_rowptr[NN + 1];
__device__ int   g_cursor[NN];
__device__ int   g_deg[NN];
__device__ int   g_eid[EE];
__device__ int   g_esrc[EE];

// ---------------- CSR build (dst-sorted edge list) ----------------
__global__ void k_zero_deg() {
    int i = blockIdx.x * blockDim.x + threadIdx.x;
    if (i < NN) g_deg[i] = 0;
}

__global__ void k_count(const int* __restrict__ ei) {
    int e = blockIdx.x * blockDim.x + threadIdx.x;
    if (e < EE) atomicAdd(&g_deg[ei[EE + e]], 1);
}

// single-block exclusive scan of degrees -> rowptr; also zero cursors
__global__ void k_scan() {
    __shared__ int sums[1024];
    const int PER = 20;  // 1024*20 >= 20000
    int tid = threadIdx.x;
    int base = tid * PER;
    int local[PER];
    int s = 0;
#pragma unroll
    for (int i = 0; i < PER; i++) {
        int idx = base + i;
        int d = (idx < NN) ? g_deg[idx] : 0;
        local[i] = s;
        s += d;
    }
    sums[tid] = s;
    __syncthreads();
    for (int off = 1; off < 1024; off <<= 1) {
        int t2 = (tid >= off) ? sums[tid - off] : 0;
        __syncthreads();
        sums[tid] += t2;
        __syncthreads();
    }
    int pre = (tid > 0) ? sums[tid - 1] : 0;
#pragma unroll
    for (int i = 0; i < PER; i++) {
        int idx = base + i;
        if (idx < NN) {
            g_rowptr[idx] = pre + local[i];
            g_cursor[idx] = 0;
        }
    }
    if (tid == 1023) g_rowptr[NN] = sums[1023];
}

__global__ void k_scatter(const int* __restrict__ ei) {
    int e = blockIdx.x * blockDim.x + threadIdx.x;
    if (e < EE) {
        int d = ei[EE + e];
        int pos = g_rowptr[d] + atomicAdd(&g_cursor[d], 1);
        g_eid[pos] = e;
        g_esrc[pos] = ei[e];
    }
}

// ---------------- edge attributes: [v_lin | sin(time2vec) | msg] ----------------
__global__ void k_edge_attr(const int* __restrict__ ei,
                            const float* __restrict__ last_update,
                            const float* __restrict__ t,
                            const float* __restrict__ msg,
                            const float* __restrict__ wlin,
                            const float* __restrict__ blin,
                            const float* __restrict__ w,
                            const float* __restrict__ b) {
    int idx = blockIdx.x * blockDim.x + threadIdx.x;
    if (idx >= EE * EDIM) return;
    int e = idx / EDIM;
    int j = idx - e * EDIM;
    float out;
    if (j < 9) {
        float rel = last_update[ei[e]] - t[e];
        if (j == 0) out = rel * wlin[0] + blin[0];
        else        out = sinf(rel * w[j - 1] + b[j - 1]);
    } else {
        out = msg[e * 64 + (j - 9)];
    }
    g_edge_attr[idx] = out;
}

// ---------------- fp32 SGEMM: C[M,N] = A[M,K] @ B[K,N] + bias ----------------
#define BM 128
#define BN 64
#define BK 16
__global__ __launch_bounds__(256) void k_sgemm(const float* __restrict__ A,
                                               const float* __restrict__ B,
                                               const float* __restrict__ bias,
                                               float* __restrict__ C,
                                               int M, int N, int K) {
    __shared__ float As[BK][BM];
    __shared__ float Bs[BK][BN];
    int tid = threadIdx.x;
    int tx = tid & 15, ty = tid >> 4;
    int row0 = blockIdx.y * BM, col0 = blockIdx.x * BN;

    float acc[8][4];
#pragma unroll
    for (int i = 0; i < 8; i++)
#pragma unroll
        for (int j = 0; j < 4; j++) acc[i][j] = 0.f;

    for (int k0 = 0; k0 < K; k0 += BK) {
#pragma unroll
        for (int i = 0; i < 8; i++) {
            int idx = tid + i * 256;          // 0..2047
            int m = idx >> 4, kk = idx & 15;
            int r = row0 + m, kg = k0 + kk;
            float v = 0.f;
            if (r < M && kg < K) v = A[r * K + kg];
            As[kk][m] = v;
        }
#pragma unroll
        for (int i = 0; i < 4; i++) {
            int idx = tid + i * 256;          // 0..1023
            int kk = idx >> 6, nn = idx & 63;
            int kg = k0 + kk;
            float v = 0.f;
            if (kg < K) v = B[kg * N + col0 + nn];
            Bs[kk][nn] = v;
        }
        __syncthreads();
#pragma unroll
        for (int kk = 0; kk < BK; kk++) {
            float4 a0 = ((float4*)As[kk])[ty * 2];
            float4 a1 = ((float4*)As[kk])[ty * 2 + 1];
            float4 b0 = ((float4*)Bs[kk])[tx];
            float av[8] = {a0.x, a0.y, a0.z, a0.w, a1.x, a1.y, a1.z, a1.w};
            float bv[4] = {b0.x, b0.y, b0.z, b0.w};
#pragma unroll
            for (int i = 0; i < 8; i++)
#pragma unroll
                for (int j = 0; j < 4; j++) acc[i][j] += av[i] * bv[j];
        }
        __syncthreads();
    }

    float4 bias4 = {0.f, 0.f, 0.f, 0.f};
    if (bias) bias4 = *(const float4*)(bias + col0 + tx * 4);
#pragma unroll
    for (int i = 0; i < 8; i++) {
        int r = row0 + ty * 8 + i;
        if (r < M) {
            float4 o = {acc[i][0] + bias4.x, acc[i][1] + bias4.y,
                        acc[i][2] + bias4.z, acc[i][3] + bias4.w};
            *(float4*)(C + r * N + col0 + tx * 4) = o;
        }
    }
}

// ---------------- attention + aggregation: one warp per (node, head) ----------------
// online softmax over the node's incoming edges (identical math to segment max softmax)
__global__ void k_attn() {
    int gw = (blockIdx.x * blockDim.x + threadIdx.x) >> 5;
    int lane = threadIdx.x & 31;
    if (gw >= NN * HH) return;
    int n = gw >> 1, h = gw & 1;
    int base = n * DD + h * CC + lane * 4;
    float4 q4 = *(const float4*)(g_q + base);
    int beg = g_rowptr[n], end = g_rowptr[n + 1];
    float m = -3.4e38f, l = 0.f;
    float ax = 0.f, ay = 0.f, az = 0.f, aw = 0.f;
    const float scale = 0.0883883476483184406f;  // 1/sqrt(128)
    for (int i = beg; i < end; i++) {
        int e = g_eid[i], s = g_esrc[i];
        int eoff = e * DD + h * CC + lane * 4;
        int noff = s * DD + h * CC + lane * 4;
        float4 e4 = *(const float4*)(g_e + eoff);
        float4 k4 = *(const float4*)(g_k + noff);
        float part = q4.x * (k4.x + e4.x) + q4.y * (k4.y + e4.y) +
                     q4.z * (k4.z + e4.z) + q4.w * (k4.w + e4.w);
#pragma unroll
        for (int off = 16; off; off >>= 1)
            part += __shfl_xor_sync(0xffffffffu, part, off);
        float alpha = part * scale;
        float4 v4 = *(const float4*)(g_v + noff);
        float mnew = fmaxf(m, alpha);
        float corr = __expf(m - mnew);
        float p = __expf(alpha - mnew);
        l = l * corr + p;
        ax = ax * corr + p * (v4.x + e4.x);
        ay = ay * corr + p * (v4.y + e4.y);
        az = az * corr + p * (v4.z + e4.z);
        aw = aw * corr + p * (v4.w + e4.w);
        m = mnew;
    }
    float inv = (l > 0.f) ? 1.f / l : 0.f;
    float4 o = {ax * inv, ay * inv, az * inv, aw * inv};
    *(float4*)(g_aggr + base) = o;
}

// ---------------- residual + layernorm + silu ----------------
__global__ void k_node_update(const float* __restrict__ ln_g,
                              const float* __restrict__ ln_b,
                              float* __restrict__ out) {
    int n = blockIdx.x, t = threadIdx.x;
    int idx = n * DD + t;
    float y = g_h[idx] + g_aggr[idx] + g_skip[idx];
    __shared__ float red[8];
    int w = t >> 5, lane = t & 31;

    float s = y;
#pragma unroll
    for (int off = 16; off; off >>= 1) s += __shfl_xor_sync(0xffffffffu, s, off);
    if (lane == 0) red[w] = s;
    __syncthreads();
    float mu = 0.f;
#pragma unroll
    for (int i = 0; i < 8; i++) mu += red[i];
    mu *= (1.f / DD);

    float d = y - mu;
    float s2 = d * d;
#pragma unroll
    for (int off = 16; off; off >>= 1) s2 += __shfl_xor_sync(0xffffffffu, s2, off);
    __syncthreads();
    if (lane == 0) red[w] = s2;
    __syncthreads();
    float var = 0.f;
#pragma unroll
    for (int i = 0; i < 8; i++) var += red[i];
    var *= (1.f / DD);

    float z = d * rsqrtf(var + 1e-5f) * ln_g[t] + ln_b[t];
    out[idx] = z / (1.f + __expf(-z));
}

// ---------------- launch ----------------
extern "C" void kernel_launch(void* const* d_in, const int* in_sizes, int n_in,
                              void* d_out, int out_size) {
    const float* x    = (const float*)d_in[0];
    const float* lu   = (const float*)d_in[1];
    const int*   ei   = (const int*)d_in[2];
    const float* t    = (const float*)d_in[3];
    const float* msg  = (const float*)d_in[4];
    const float* wlin = (const float*)d_in[5];
    const float* blin = (const float*)d_in[6];
    const float* w    = (const float*)d_in[7];
    const float* b    = (const float*)d_in[8];
    const float* lin_w = (const float*)d_in[9];
    const float* lin_b = (const float*)d_in[10];
    const float* Wq = (const float*)d_in[11];
    const float* bq = (const float*)d_in[12];
    const float* Wk = (const float*)d_in[13];
    const float* bk = (const float*)d_in[14];
    const float* Wv = (const float*)d_in[15];
    const float* bv = (const float*)d_in[16];
    const float* We = (const float*)d_in[17];
    const float* Ws = (const float*)d_in[18];
    const float* bs = (const float*)d_in[19];
    const float* lng = (const float*)d_in[20];
    const float* lnb = (const float*)d_in[21];
    float* out = (float*)d_out;

    void* p;
    cudaGetSymbolAddress(&p, g_edge_attr); float* pea = (float*)p;
    cudaGetSymbolAddress(&p, g_h);    float* ph = (float*)p;
    cudaGetSymbolAddress(&p, g_q);    float* pq = (float*)p;
    cudaGetSymbolAddress(&p, g_k);    float* pk = (float*)p;
    cudaGetSymbolAddress(&p, g_v);    float* pv = (float*)p;
    cudaGetSymbolAddress(&p, g_skip); float* ps = (float*)p;
    cudaGetSymbolAddress(&p, g_e);    float* pe = (float*)p;

    // CSR build (dst no longer changes; rebuilt every call for determinism of work)
    k_zero_deg<<<(NN + 255) / 256, 256>>>();
    k_count<<<(EE + 255) / 256, 256>>>(ei);
    k_scan<<<1, 1024>>>();
    k_scatter<<<(EE + 255) / 256, 256>>>(ei);
    k_edge_attr<<<(EE * EDIM + 255) / 256, 256>>>(ei, lu, t, msg, wlin, blin, w, b);

    dim3 gn(DD / BN, (NN + BM - 1) / BM);
    dim3 ge(DD / BN, (EE + BM - 1) / BM);

    // input projection
    k_sgemm<<<gn, 256>>>(x, lin_w, lin_b, ph, NN, DD, 100);

    for (int i = 0; i < LL; i++) {
        k_sgemm<<<gn, 256>>>(ph, Wq + i * DD * DD, bq + i * DD, pq, NN, DD, DD);
        k_sgemm<<<gn, 256>>>(ph, Wk + i * DD * DD, bk + i * DD, pk, NN, DD, DD);
        k_sgemm<<<gn, 256>>>(ph, Wv + i * DD * DD, bv + i * DD, pv, NN, DD, DD);
        k_sgemm<<<gn, 256>>>(ph, Ws + i * DD * DD, bs + i * DD, ps, NN, DD, DD);
        k_sgemm<<<ge, 256>>>(pea, We + i * EDIM * DD, (const float*)nullptr, pe, EE, DD, EDIM);
        k_attn<<<(NN * HH * 32 + 255) / 256, 256>>>();
        k_node_update<<<NN, DD>>>(lng + i * DD, lnb + i * DD, (i == LL - 1) ? out : ph);
    }
}

// round 5
// speedup vs baseline: 1.2081x; 1.2081x over previous
#include <cuda_runtime.h>
#include <math.h>
#include <stdint.h>

#define NN 20000
#define EE 320000
#define DD 256
#define HH 2
#define CC 128
#define EKP 80     // padded edge-attr width (real 73, zero-padded)
#define EKR 73
#define LL 3

// ---------------- scratch (static __device__, no allocation) ----------------
__device__ float g_edge_attr[EE * EKP];    // 102 MB, rows 16B-aligned
__device__ float g_h[NN * DD];
__device__ float g_q[NN * DD];
__device__ float g_k[NN * DD];
__device__ float g_v[NN * DD];
__device__ float g_skip[NN * DD];
__device__ float g_e[EE * DD];             // 328 MB
__device__ float g_aggr[NN * DD];
__device__ int   g_rowptr[NN + 1];
__device__ int   g_cursor[NN];
__device__ int   g_deg[NN];
__device__ int   g_eid[EE];
__device__ int   g_esrc[EE];

// ---------------- CSR build (dst-sorted edge list) ----------------
__global__ void k_zero_deg() {
    int i = blockIdx.x * blockDim.x + threadIdx.x;
    if (i < NN) g_deg[i] = 0;
}

__global__ void k_count(const int* __restrict__ ei) {
    int e = blockIdx.x * blockDim.x + threadIdx.x;
    if (e < EE) atomicAdd(&g_deg[ei[EE + e]], 1);
}

__global__ void k_scan() {
    __shared__ int sums[1024];
    const int PER = 20;
    int tid = threadIdx.x;
    int base = tid * PER;
    int local[PER];
    int s = 0;
#pragma unroll
    for (int i = 0; i < PER; i++) {
        int idx = base + i;
        int d = (idx < NN) ? g_deg[idx] : 0;
        local[i] = s;
        s += d;
    }
    sums[tid] = s;
    __syncthreads();
    for (int off = 1; off < 1024; off <<= 1) {
        int t2 = (tid >= off) ? sums[tid - off] : 0;
        __syncthreads();
        sums[tid] += t2;
        __syncthreads();
    }
    int pre = (tid > 0) ? sums[tid - 1] : 0;
#pragma unroll
    for (int i = 0; i < PER; i++) {
        int idx = base + i;
        if (idx < NN) {
            g_rowptr[idx] = pre + local[i];
            g_cursor[idx] = 0;
        }
    }
    if (tid == 1023) g_rowptr[NN] = sums[1023];
}

__global__ void k_scatter(const int* __restrict__ ei) {
    int e = blockIdx.x * blockDim.x + threadIdx.x;
    if (e < EE) {
        int d = ei[EE + e];
        int pos = g_rowptr[d] + atomicAdd(&g_cursor[d], 1);
        g_eid[pos] = e;
        g_esrc[pos] = ei[e];
    }
}

// ---------------- edge attributes: [v_lin | sin(time2vec) | msg | 0-pad] ----------------
__global__ void k_edge_attr(const int* __restrict__ ei,
                            const float* __restrict__ last_update,
                            const float* __restrict__ t,
                            const float* __restrict__ msg,
                            const float* __restrict__ wlin,
                            const float* __restrict__ blin,
                            const float* __restrict__ w,
                            const float* __restrict__ b) {
    int idx = blockIdx.x * blockDim.x + threadIdx.x;
    if (idx >= EE * EKP) return;
    int e = idx / EKP;
    int j = idx - e * EKP;
    float out;
    if (j < 9) {
        float rel = last_update[ei[e]] - t[e];
        if (j == 0) out = rel * wlin[0] + blin[0];
        else        out = sinf(rel * w[j - 1] + b[j - 1]);
    } else if (j < EKR) {
        out = msg[e * 64 + (j - 9)];
    } else {
        out = 0.f;
    }
    g_edge_attr[idx] = out;
}

// ---------------- 3xTF32 tensor-core GEMM ----------------
// C[M,256] = A[M,K] @ B[K,256] (+bias). A rows K-strided (K % 4 == 0, rows 16B aligned).
// B rows beyond KB are treated as zero (handles K padded > KB real).
__device__ __forceinline__ void split2(float x, float& hi, float& lo) {
    uint32_t u;
    asm("cvt.rna.tf32.f32 %0, %1;" : "=r"(u) : "f"(x));
    hi = __uint_as_float(u);
    float r = x - hi;
    asm("cvt.rna.tf32.f32 %0, %1;" : "=r"(u) : "f"(r));
    lo = __uint_as_float(u);
}

__device__ __forceinline__ void mma8(float* d, const uint32_t* a, const uint32_t* b) {
    asm volatile(
        "mma.sync.aligned.m16n8k8.row.col.f32.tf32.tf32.f32 "
        "{%0,%1,%2,%3}, {%4,%5,%6,%7}, {%8,%9}, {%0,%1,%2,%3};\n"
        : "+f"(d[0]), "+f"(d[1]), "+f"(d[2]), "+f"(d[3])
        : "r"(a[0]), "r"(a[1]), "r"(a[2]), "r"(a[3]), "r"(b[0]), "r"(b[1]));
}

#define BM 128
#define BN 128
#define BKT 16
#define ASTR (BM + 8)   // 136: conflict-free fragment LDS
#define BSTR (BN + 8)

__global__ __launch_bounds__(256, 1) void k_mma(const float* __restrict__ A,
                                                const float* __restrict__ B,
                                                const float* __restrict__ bias,
                                                float* __restrict__ C,
                                                int M, int K, int KB) {
    __shared__ float Ah[BKT][ASTR];
    __shared__ float Al[BKT][ASTR];
    __shared__ float Bh[BKT][BSTR];
    __shared__ float Bl[BKT][BSTR];

    const int tid = threadIdx.x;
    const int warp = tid >> 5, lane = tid & 31;
    const int g = lane >> 2, tig = lane & 3;
    const int wm = (warp & 1) * 64;   // 2 warps along M (64 rows each)
    const int wn = (warp >> 1) * 32;  // 4 warps along N (32 cols each)
    const int row0 = blockIdx.y * BM;
    const int col0 = blockIdx.x * BN;

    float d[4][4][4];
#pragma unroll
    for (int mi = 0; mi < 4; mi++)
#pragma unroll
        for (int ni = 0; ni < 4; ni++)
#pragma unroll
            for (int r = 0; r < 4; r++) d[mi][ni][r] = 0.f;

    for (int k0 = 0; k0 < K; k0 += BKT) {
        // ---- load A tile (128 x 16), split hi/lo, store transposed ----
#pragma unroll
        for (int i = 0; i < 2; i++) {
            int idx = tid + i * 256;
            int r = idx >> 2;
            int kq = (idx & 3) << 2;
            int gr = row0 + r;
            int kg = k0 + kq;
            float4 v = make_float4(0.f, 0.f, 0.f, 0.f);
            if (gr < M && kg + 3 < K) v = *(const float4*)(A + (size_t)gr * K + kg);
            float h, l;
            split2(v.x, h, l); Ah[kq + 0][r] = h; Al[kq + 0][r] = l;
            split2(v.y, h, l); Ah[kq + 1][r] = h; Al[kq + 1][r] = l;
            split2(v.z, h, l); Ah[kq + 2][r] = h; Al[kq + 2][r] = l;
            split2(v.w, h, l); Ah[kq + 3][r] = h; Al[kq + 3][r] = l;
        }
        // ---- load B tile (16 x 128), split hi/lo ----
#pragma unroll
        for (int i = 0; i < 2; i++) {
            int idx = tid + i * 256;
            int kk = idx >> 5;
            int nq = (idx & 31) << 2;
            int kg = k0 + kk;
            float4 v = make_float4(0.f, 0.f, 0.f, 0.f);
            if (kg < KB) v = *(const float4*)(B + (size_t)kg * DD + col0 + nq);
            float4 hv, lv;
            split2(v.x, hv.x, lv.x);
            split2(v.y, hv.y, lv.y);
            split2(v.z, hv.z, lv.z);
            split2(v.w, hv.w, lv.w);
            *(float4*)&Bh[kk][nq] = hv;
            *(float4*)&Bl[kk][nq] = lv;
        }
        __syncthreads();

#pragma unroll
        for (int ks = 0; ks < BKT; ks += 8) {
            uint32_t ah[16], al[16], bh[8], bl[8];
#pragma unroll
            for (int mi = 0; mi < 4; mi++) {
                int rb = wm + mi * 16;
                ah[mi * 4 + 0] = __float_as_uint(Ah[ks + tig][rb + g]);
                ah[mi * 4 + 1] = __float_as_uint(Ah[ks + tig][rb + g + 8]);
                ah[mi * 4 + 2] = __float_as_uint(Ah[ks + tig + 4][rb + g]);
                ah[mi * 4 + 3] = __float_as_uint(Ah[ks + tig + 4][rb + g + 8]);
                al[mi * 4 + 0] = __float_as_uint(Al[ks + tig][rb + g]);
                al[mi * 4 + 1] = __float_as_uint(Al[ks + tig][rb + g + 8]);
                al[mi * 4 + 2] = __float_as_uint(Al[ks + tig + 4][rb + g]);
                al[mi * 4 + 3] = __float_as_uint(Al[ks + tig + 4][rb + g + 8]);
            }
#pragma unroll
            for (int ni = 0; ni < 4; ni++) {
                int cb = wn + ni * 8;
                bh[ni * 2 + 0] = __float_as_uint(Bh[ks + tig][cb + g]);
                bh[ni * 2 + 1] = __float_as_uint(Bh[ks + tig + 4][cb + g]);
                bl[ni * 2 + 0] = __float_as_uint(Bl[ks + tig][cb + g]);
                bl[ni * 2 + 1] = __float_as_uint(Bl[ks + tig + 4][cb + g]);
            }
#pragma unroll
            for (int mi = 0; mi < 4; mi++)
#pragma unroll
                for (int ni = 0; ni < 4; ni++) {
                    mma8(d[mi][ni], &ah[mi * 4], &bh[ni * 2]);
                    mma8(d[mi][ni], &ah[mi * 4], &bl[ni * 2]);
                    mma8(d[mi][ni], &al[mi * 4], &bh[ni * 2]);
                }
        }
        __syncthreads();
    }

    // ---- epilogue: bias + store (float2 per fragment row) ----
#pragma unroll
    for (int ni = 0; ni < 4; ni++) {
        int col = col0 + wn + ni * 8 + tig * 2;
        float2 bz = make_float2(0.f, 0.f);
        if (bias) bz = *(const float2*)(bias + col);
#pragma unroll
        for (int mi = 0; mi < 4; mi++) {
            int r = row0 + wm + mi * 16 + g;
            if (r < M) {
                float2 o = make_float2(d[mi][ni][0] + bz.x, d[mi][ni][1] + bz.y);
                *(float2*)(C + (size_t)r * DD + col) = o;
            }
            if (r + 8 < M) {
                float2 o = make_float2(d[mi][ni][2] + bz.x, d[mi][ni][3] + bz.y);
                *(float2*)(C + (size_t)(r + 8) * DD + col) = o;
            }
        }
    }
}

// ---------------- attention + aggregation: one warp per (node, head) ----------------
__global__ void k_attn() {
    int gw = (blockIdx.x * blockDim.x + threadIdx.x) >> 5;
    int lane = threadIdx.x & 31;
    if (gw >= NN * HH) return;
    int n = gw >> 1, h = gw & 1;
    int base = n * DD + h * CC + lane * 4;
    float4 q4 = *(const float4*)(g_q + base);
    int beg = g_rowptr[n], end = g_rowptr[n + 1];
    float m = -3.4e38f, l = 0.f;
    float ax = 0.f, ay = 0.f, az = 0.f, aw = 0.f;
    const float scale = 0.0883883476483184406f;  // 1/sqrt(128)
    for (int i = beg; i < end; i++) {
        int e = g_eid[i], s = g_esrc[i];
        int eoff = e * DD + h * CC + lane * 4;
        int noff = s * DD + h * CC + lane * 4;
        float4 e4 = *(const float4*)(g_e + eoff);
        float4 k4 = *(const float4*)(g_k + noff);
        float part = q4.x * (k4.x + e4.x) + q4.y * (k4.y + e4.y) +
                     q4.z * (k4.z + e4.z) + q4.w * (k4.w + e4.w);
#pragma unroll
        for (int off = 16; off; off >>= 1)
            part += __shfl_xor_sync(0xffffffffu, part, off);
        float alpha = part * scale;
        float4 v4 = *(const float4*)(g_v + noff);
        float mnew = fmaxf(m, alpha);
        float corr = __expf(m - mnew);
        float p = __expf(alpha - mnew);
        l = l * corr + p;
        ax = ax * corr + p * (v4.x + e4.x);
        ay = ay * corr + p * (v4.y + e4.y);
        az = az * corr + p * (v4.z + e4.z);
        aw = aw * corr + p * (v4.w + e4.w);
        m = mnew;
    }
    float inv = (l > 0.f) ? 1.f / l : 0.f;
    float4 o = {ax * inv, ay * inv, az * inv, aw * inv};
    *(float4*)(g_aggr + base) = o;
}

// ---------------- residual + layernorm + silu ----------------
__global__ void k_node_update(const float* __restrict__ ln_g,
                              const float* __restrict__ ln_b,
                              float* __restrict__ out) {
    int n = blockIdx.x, t = threadIdx.x;
    int idx = n * DD + t;
    float y = g_h[idx] + g_aggr[idx] + g_skip[idx];
    __shared__ float red[8];
    int w = t >> 5, lane = t & 31;

    float s = y;
#pragma unroll
    for (int off = 16; off; off >>= 1) s += __shfl_xor_sync(0xffffffffu, s, off);
    if (lane == 0) red[w] = s;
    __syncthreads();
    float mu = 0.f;
#pragma unroll
    for (int i = 0; i < 8; i++) mu += red[i];
    mu *= (1.f / DD);

    float d = y - mu;
    float s2 = d * d;
#pragma unroll
    for (int off = 16; off; off >>= 1) s2 += __shfl_xor_sync(0xffffffffu, s2, off);
    __syncthreads();
    if (lane == 0) red[w] = s2;
    __syncthreads();
    float var = 0.f;
#pragma unroll
    for (int i = 0; i < 8; i++) var += red[i];
    var *= (1.f / DD);

    float z = d * rsqrtf(var + 1e-5f) * ln_g[t] + ln_b[t];
    out[idx] = z / (1.f + __expf(-z));
}

// ---------------- launch ----------------
extern "C" void kernel_launch(void* const* d_in, const int* in_sizes, int n_in,
                              void* d_out, int out_size) {
    const float* x    = (const float*)d_in[0];
    const float* lu   = (const float*)d_in[1];
    const int*   ei   = (const int*)d_in[2];
    const float* t    = (const float*)d_in[3];
    const float* msg  = (const float*)d_in[4];
    const float* wlin = (const float*)d_in[5];
    const float* blin = (const float*)d_in[6];
    const float* w    = (const float*)d_in[7];
    const float* b    = (const float*)d_in[8];
    const float* lin_w = (const float*)d_in[9];
    const float* lin_b = (const float*)d_in[10];
    const float* Wq = (const float*)d_in[11];
    const float* bq = (const float*)d_in[12];
    const float* Wk = (const float*)d_in[13];
    const float* bk = (const float*)d_in[14];
    const float* Wv = (const float*)d_in[15];
    const float* bv = (const float*)d_in[16];
    const float* We = (const float*)d_in[17];
    const float* Ws = (const float*)d_in[18];
    const float* bs = (const float*)d_in[19];
    const float* lng = (const float*)d_in[20];
    const float* lnb = (const float*)d_in[21];
    float* out = (float*)d_out;

    void* p;
    cudaGetSymbolAddress(&p, g_edge_attr); float* pea = (float*)p;
    cudaGetSymbolAddress(&p, g_h);    float* ph = (float*)p;
    cudaGetSymbolAddress(&p, g_q);    float* pq = (float*)p;
    cudaGetSymbolAddress(&p, g_k);    float* pk = (float*)p;
    cudaGetSymbolAddress(&p, g_v);    float* pv = (float*)p;
    cudaGetSymbolAddress(&p, g_skip); float* ps = (float*)p;
    cudaGetSymbolAddress(&p, g_e);    float* pe = (float*)p;

    // CSR build + edge attributes
    k_zero_deg<<<(NN + 255) / 256, 256>>>();
    k_count<<<(EE + 255) / 256, 256>>>(ei);
    k_scan<<<1, 1024>>>();
    k_scatter<<<(EE + 255) / 256, 256>>>(ei);
    k_edge_attr<<<(EE * EKP + 255) / 256, 256>>>(ei, lu, t, msg, wlin, blin, w, b);

    dim3 gn(DD / BN, (NN + BM - 1) / BM);   // (2, 157)
    dim3 ge(DD / BN, EE / BM);              // (2, 2500)

    // input projection: K=100
    k_mma<<<gn, 256>>>(x, lin_w, lin_b, ph, NN, 100, 100);

    for (int i = 0; i < LL; i++) {
        k_mma<<<gn, 256>>>(ph, Wq + i * DD * DD, bq + i * DD, pq, NN, DD, DD);
        k_mma<<<gn, 256>>>(ph, Wk + i * DD * DD, bk + i * DD, pk, NN, DD, DD);
        k_mma<<<gn, 256>>>(ph, Wv + i * DD * DD, bv + i * DD, pv, NN, DD, DD);
        k_mma<<<gn, 256>>>(ph, Ws + i * DD * DD, bs + i * DD, ps, NN, DD, DD);
        k_mma<<<ge, 256>>>(pea, We + i * EKR * DD, (const float*)nullptr, pe, EE, EKP, EKR);
        k_attn<<<(NN * HH * 32 + 255) / 256, 256>>>();
        k_node_update<<<NN, DD>>>(lng + i * DD, lnb + i * DD, (i == LL - 1) ? out : ph);
    }
}

// round 9
// speedup vs baseline: 1.6591x; 1.3733x over previous
#include <cuda_runtime.h>
#include <cuda_bf16.h>
#include <math.h>
#include <stdint.h>

#define NN 20000
#define EE 320000
#define DD 256
#define HH 2
#define CC 128
#define LL 3

// ---------------- scratch (static __device__, no allocation) ----------------
__device__ __nv_bfloat16 g_ea_hi[EE * 128];   // edge attr split, K padded to 128
__device__ __nv_bfloat16 g_ea_lo[EE * 128];
__device__ __nv_bfloat16 g_h_hi[NN * 256];
__device__ __nv_bfloat16 g_h_lo[NN * 256];
__device__ __nv_bfloat16 g_x_hi[NN * 128];    // input x split, K padded to 128
__device__ __nv_bfloat16 g_x_lo[NN * 128];
__device__ __nv_bfloat16 g_wn_hi[12 * 256 * 256];  // Q/K/V/skip x 3 layers, [N][K] K-major
__device__ __nv_bfloat16 g_wn_lo[12 * 256 * 256];
__device__ __nv_bfloat16 g_we_hi[3 * 256 * 128];   // We, K padded 73->128, [N][K]
__device__ __nv_bfloat16 g_we_lo[3 * 256 * 128];
__device__ __nv_bfloat16 g_wl_hi[256 * 128];       // lin_w, K padded 100->128, [N][K]
__device__ __nv_bfloat16 g_wl_lo[256 * 128];

__device__ float g_h[NN * DD];
__device__ float g_q[NN * DD];
__device__ float g_k[NN * DD];
__device__ float g_v[NN * DD];
__device__ float g_skip[NN * DD];
__device__ float g_e[EE * DD];             // 328 MB
__device__ float g_aggr[NN * DD];
__device__ int   g_rowptr[NN + 1];
__device__ int   g_cursor[NN];
__device__ int   g_deg[NN];
__device__ int   g_eid[EE];
__device__ int   g_esrc[EE];

__device__ __forceinline__ uint32_t smem_u32(const void* p) {
    uint32_t a;
    asm("{ .reg .u64 t; cvta.to.shared.u64 t, %1; cvt.u32.u64 %0, t; }" : "=r"(a) : "l"(p));
    return a;
}
__device__ __forceinline__ void splitbf(float x, __nv_bfloat16& h, __nv_bfloat16& l) {
    h = __float2bfloat16(x);
    l = __float2bfloat16(x - __bfloat162float(h));
}

// ---------------- CSR build ----------------
__global__ void k_zero_deg() {
    int i = blockIdx.x * blockDim.x + threadIdx.x;
    if (i < NN) g_deg[i] = 0;
}
__global__ void k_count(const int* __restrict__ ei) {
    int e = blockIdx.x * blockDim.x + threadIdx.x;
    if (e < EE) atomicAdd(&g_deg[ei[EE + e]], 1);
}
__global__ void k_scan() {
    __shared__ int sums[1024];
    const int PER = 20;
    int tid = threadIdx.x;
    int base = tid * PER;
    int local[PER];
    int s = 0;
#pragma unroll
    for (int i = 0; i < PER; i++) {
        int idx = base + i;
        int d = (idx < NN) ? g_deg[idx] : 0;
        local[i] = s;
        s += d;
    }
    sums[tid] = s;
    __syncthreads();
    for (int off = 1; off < 1024; off <<= 1) {
        int t2 = (tid >= off) ? sums[tid - off] : 0;
        __syncthreads();
        sums[tid] += t2;
        __syncthreads();
    }
    int pre = (tid > 0) ? sums[tid - 1] : 0;
#pragma unroll
    for (int i = 0; i < PER; i++) {
        int idx = base + i;
        if (idx < NN) {
            g_rowptr[idx] = pre + local[i];
            g_cursor[idx] = 0;
        }
    }
    if (tid == 1023) g_rowptr[NN] = sums[1023];
}
__global__ void k_scatter(const int* __restrict__ ei) {
    int e = blockIdx.x * blockDim.x + threadIdx.x;
    if (e < EE) {
        int d = ei[EE + e];
        int pos = g_rowptr[d] + atomicAdd(&g_cursor[d], 1);
        g_eid[pos] = e;
        g_esrc[pos] = ei[e];
    }
}

// ---------------- edge attributes, split to bf16 hi/lo, K padded to 128 ----------------
__global__ void k_edge_attr(const int* __restrict__ ei,
                            const float* __restrict__ last_update,
                            const float* __restrict__ t,
                            const float* __restrict__ msg,
                            const float* __restrict__ wlin,
                            const float* __restrict__ blin,
                            const float* __restrict__ w,
                            const float* __restrict__ b) {
    int idx = blockIdx.x * blockDim.x + threadIdx.x;
    if (idx >= EE * 128) return;
    int e = idx >> 7;
    int j = idx & 127;
    float v;
    if (j < 9) {
        float rel = last_update[ei[e]] - t[e];
        if (j == 0) v = rel * wlin[0] + blin[0];
        else        v = sinf(rel * w[j - 1] + b[j - 1]);
    } else if (j < 73) {
        v = msg[e * 64 + (j - 9)];
    } else {
        v = 0.f;
    }
    splitbf(v, g_ea_hi[idx], g_ea_lo[idx]);
}

// ---------------- weight / activation split kernels ----------------
__global__ void k_split_wn(const float* __restrict__ Wq, const float* __restrict__ Wk,
                           const float* __restrict__ Wv, const float* __restrict__ Ws) {
    int idx = blockIdx.x * blockDim.x + threadIdx.x;
    if (idx >= 12 * 65536) return;
    int mat = idx >> 16;
    int r = idx & 65535;
    int n = r >> 8, k = r & 255;
    int layer = mat >> 2, ty = mat & 3;
    const float* W = (ty == 0 ? Wq : ty == 1 ? Wk : ty == 2 ? Wv : Ws) + layer * 65536;
    splitbf(W[k * 256 + n], g_wn_hi[idx], g_wn_lo[idx]);
}
__global__ void k_split_we(const float* __restrict__ We) {
    int idx = blockIdx.x * blockDim.x + threadIdx.x;
    if (idx >= 3 * 32768) return;
    int mat = idx >> 15;
    int r = idx & 32767;
    int n = r >> 7, k = r & 127;
    float v = (k < 73) ? We[mat * 73 * 256 + k * 256 + n] : 0.f;
    splitbf(v, g_we_hi[idx], g_we_lo[idx]);
}
__global__ void k_split_wl(const float* __restrict__ lin_w) {
    int idx = blockIdx.x * blockDim.x + threadIdx.x;
    if (idx >= 32768) return;
    int n = idx >> 7, k = idx & 127;
    float v = (k < 100) ? lin_w[k * 256 + n] : 0.f;
    splitbf(v, g_wl_hi[idx], g_wl_lo[idx]);
}
__global__ void k_split_x(const float* __restrict__ x) {
    int idx = blockIdx.x * blockDim.x + threadIdx.x;
    if (idx >= NN * 128) return;
    int m = idx >> 7, k = idx & 127;
    float v = (k < 100) ? x[m * 100 + k] : 0.f;
    splitbf(v, g_x_hi[idx], g_x_lo[idx]);
}
__global__ void k_split_h() {
    int idx = blockIdx.x * blockDim.x + threadIdx.x;
    if (idx >= NN * 256) return;
    splitbf(g_h[idx], g_h_hi[idx], g_h_lo[idx]);
}

// ---------------- split-bf16 mma.sync GEMM with cp.async + ldmatrix ----------------
// C[M,256] = A@B^T + bias.  A hi/lo: [M][K] bf16 K-contiguous; B hi/lo: [256][K] bf16.
// CTA tile 128x128, K-tile 32. Warp tile 64x32 (2x4 warps). 3 mma terms per k16.
#define LDT 40                       // smem row stride in bf16 (80 B: 16B-aligned, conflict-free)
#define TILE_B (128 * LDT * 2)       // 10240 B per operand tile
#define STAGE_B (4 * TILE_B)         // Ah, Al, Bh, Bl
#define SMEM_MM (2 * STAGE_B)        // 81920 B

__device__ __forceinline__ void mma16816(float* d, const uint32_t* a, const uint32_t* b) {
    asm volatile(
        "mma.sync.aligned.m16n8k16.row.col.f32.bf16.bf16.f32 "
        "{%0,%1,%2,%3},{%4,%5,%6,%7},{%8,%9},{%0,%1,%2,%3};"
        : "+f"(d[0]), "+f"(d[1]), "+f"(d[2]), "+f"(d[3])
        : "r"(a[0]), "r"(a[1]), "r"(a[2]), "r"(a[3]), "r"(b[0]), "r"(b[1]));
}
__device__ __forceinline__ void ldm4(uint32_t* r, uint32_t addr) {
    asm volatile("ldmatrix.sync.aligned.m8n8.x4.shared.b16 {%0,%1,%2,%3}, [%4];"
                 : "=r"(r[0]), "=r"(r[1]), "=r"(r[2]), "=r"(r[3]) : "r"(addr));
}
__device__ __forceinline__ void cp16(uint32_t dst, const void* src, int szr) {
    asm volatile("cp.async.cg.shared.global [%0], [%1], 16, %2;"
                 :: "r"(dst), "l"(src), "r"(szr));
}

__device__ __forceinline__ void mm_load_stage(
    uint32_t sbase, int st, int kt, int row0, int col0, int M, int K,
    const __nv_bfloat16* Ah, const __nv_bfloat16* Al,
    const __nv_bfloat16* Bh, const __nv_bfloat16* Bl, int tid) {
    int kg0 = kt * 32;
#pragma unroll
    for (int i = 0; i < 8; i++) {
        int c = tid + i * 256;                 // 0..2047
        int op = c >> 9;                       // 0:Ah 1:Al 2:Bh 3:Bl
        int r = (c >> 2) & 127, seg = c & 3;
        const __nv_bfloat16* S = (op == 0) ? Ah : (op == 1) ? Al : (op == 2) ? Bh : Bl;
        int gr = (op < 2) ? (row0 + r) : (col0 + r);
        int valid = (op < 2) ? (gr < M) : 1;
        uint32_t dst = sbase + st * STAGE_B + op * TILE_B + r * (LDT * 2) + seg * 16;
        const __nv_bfloat16* src = S + (valid ? ((size_t)gr * K + kg0 + seg * 8) : 0);
        cp16(dst, src, valid ? 16 : 0);
    }
}

__global__ __launch_bounds__(256) void k_mma(
    const __nv_bfloat16* __restrict__ Ah, const __nv_bfloat16* __restrict__ Al,
    const __nv_bfloat16* __restrict__ Bh, const __nv_bfloat16* __restrict__ Bl,
    const float* __restrict__ bias, float* __restrict__ C, int M, int K) {
    extern __shared__ char sm[];
    uint32_t sbase = smem_u32(sm);
    int tid = threadIdx.x, warp = tid >> 5, lane = tid & 31;
    int g = lane >> 2, tig = lane & 3;
    int wm = (warp & 1) * 64, wn = (warp >> 1) * 32;
    int row0 = blockIdx.y * 128, col0 = blockIdx.x * 128;
    int nkt = K >> 5;

    float acc[4][4][4];
#pragma unroll
    for (int mi = 0; mi < 4; mi++)
#pragma unroll
        for (int ni = 0; ni < 4; ni++)
#pragma unroll
            for (int r = 0; r < 4; r++) acc[mi][ni][r] = 0.f;

    mm_load_stage(sbase, 0, 0, row0, col0, M, K, Ah, Al, Bh, Bl, tid);
    asm volatile("cp.async.commit_group;");

    for (int kt = 0; kt < nkt; kt++) {
        if (kt + 1 < nkt) {
            mm_load_stage(sbase, (kt + 1) & 1, kt + 1, row0, col0, M, K, Ah, Al, Bh, Bl, tid);
            asm volatile("cp.async.commit_group;");
            asm volatile("cp.async.wait_group 1;");
        } else {
            asm volatile("cp.async.wait_group 0;");
        }
        __syncthreads();

        uint32_t at  = sbase + (kt & 1) * STAGE_B;
        uint32_t alt = at + TILE_B;
        uint32_t bt  = at + 2 * TILE_B;
        uint32_t blt = at + 3 * TILE_B;
        int arow = (lane & 15);
        int acol = (lane >> 4) * 8;
#pragma unroll
        for (int ks = 0; ks < 32; ks += 16) {
            uint32_t rah[4][4], ral[4][4], rbh[4][2], rbl[4][2];
#pragma unroll
            for (int mi = 0; mi < 4; mi++) {
                uint32_t off = ((wm + mi * 16 + arow) * LDT + ks + acol) * 2;
                ldm4(rah[mi], at + off);
                ldm4(ral[mi], alt + off);
            }
#pragma unroll
            for (int ni = 0; ni < 4; ni++) {
                uint32_t off = ((wn + ni * 8 + g) * LDT + ks + 2 * tig) * 2;
                rbh[ni][0] = *(const uint32_t*)(sm + (bt - sbase) + off);
                rbh[ni][1] = *(const uint32_t*)(sm + (bt - sbase) + off + 16);
                rbl[ni][0] = *(const uint32_t*)(sm + (blt - sbase) + off);
                rbl[ni][1] = *(const uint32_t*)(sm + (blt - sbase) + off + 16);
            }
#pragma unroll
            for (int mi = 0; mi < 4; mi++)
#pragma unroll
                for (int ni = 0; ni < 4; ni++) {
                    mma16816(acc[mi][ni], rah[mi], rbh[ni]);
                    mma16816(acc[mi][ni], rah[mi], rbl[ni]);
                    mma16816(acc[mi][ni], ral[mi], rbh[ni]);
                }
        }
        __syncthreads();
    }

    // epilogue: bias + store (float2 per fragment half-row)
#pragma unroll
    for (int ni = 0; ni < 4; ni++) {
        int col = col0 + wn + ni * 8 + 2 * tig;
        float2 bz = make_float2(0.f, 0.f);
        if (bias) bz = *(const float2*)(bias + col);
#pragma unroll
        for (int mi = 0; mi < 4; mi++) {
            int r = row0 + wm + mi * 16 + g;
            if (r < M) {
                float2 o = make_float2(acc[mi][ni][0] + bz.x, acc[mi][ni][1] + bz.y);
                *(float2*)(C + (size_t)r * 256 + col) = o;
            }
            if (r + 8 < M) {
                float2 o = make_float2(acc[mi][ni][2] + bz.x, acc[mi][ni][3] + bz.y);
                *(float2*)(C + (size_t)(r + 8) * 256 + col) = o;
            }
        }
    }
}

// ---------------- attention + aggregation: one warp per (node, head) ----------------
__global__ void k_attn() {
    int gw = (blockIdx.x * blockDim.x + threadIdx.x) >> 5;
    int lane = threadIdx.x & 31;
    if (gw >= NN * HH) return;
    int n = gw >> 1, h = gw & 1;
    int base = n * DD + h * CC + lane * 4;
    float4 q4 = *(const float4*)(g_q + base);
    int beg = g_rowptr[n], end = g_rowptr[n + 1];
    float m = -3.4e38f, l = 0.f;
    float ax = 0.f, ay = 0.f, az = 0.f, aw = 0.f;
    const float scale = 0.0883883476483184406f;  // 1/sqrt(128)
    for (int i = beg; i < end; i++) {
        int e = g_eid[i], s = g_esrc[i];
        int eoff = e * DD + h * CC + lane * 4;
        int noff = s * DD + h * CC + lane * 4;
        float4 e4 = *(const float4*)(g_e + eoff);
        float4 k4 = *(const float4*)(g_k + noff);
        float part = q4.x * (k4.x + e4.x) + q4.y * (k4.y + e4.y) +
                     q4.z * (k4.z + e4.z) + q4.w * (k4.w + e4.w);
#pragma unroll
        for (int off = 16; off; off >>= 1)
            part += __shfl_xor_sync(0xffffffffu, part, off);
        float alpha = part * scale;
        float4 v4 = *(const float4*)(g_v + noff);
        float mnew = fmaxf(m, alpha);
        float corr = __expf(m - mnew);
        float p = __expf(alpha - mnew);
        l = l * corr + p;
        ax = ax * corr + p * (v4.x + e4.x);
        ay = ay * corr + p * (v4.y + e4.y);
        az = az * corr + p * (v4.z + e4.z);
        aw = aw * corr + p * (v4.w + e4.w);
        m = mnew;
    }
    float inv = (l > 0.f) ? 1.f / l : 0.f;
    float4 o = {ax * inv, ay * inv, az * inv, aw * inv};
    *(float4*)(g_aggr + base) = o;
}

// ---------------- residual + layernorm + silu (+ fused bf16 split of new h) ----------------
__global__ void k_node_update(const float* __restrict__ ln_g,
                              const float* __restrict__ ln_b,
                              float* __restrict__ out) {
    int n = blockIdx.x, t = threadIdx.x;
    int idx = n * DD + t;
    float y = g_h[idx] + g_aggr[idx] + g_skip[idx];
    __shared__ float red[8];
    int w = t >> 5, lane = t & 31;

    float s = y;
#pragma unroll
    for (int off = 16; off; off >>= 1) s += __shfl_xor_sync(0xffffffffu, s, off);
    if (lane == 0) red[w] = s;
    __syncthreads();
    float mu = 0.f;
#pragma unroll
    for (int i = 0; i < 8; i++) mu += red[i];
    mu *= (1.f / DD);

    float d = y - mu;
    float s2 = d * d;
#pragma unroll
    for (int off = 16; off; off >>= 1) s2 += __shfl_xor_sync(0xffffffffu, s2, off);
    __syncthreads();
    if (lane == 0) red[w] = s2;
    __syncthreads();
    float var = 0.f;
#pragma unroll
    for (int i = 0; i < 8; i++) var += red[i];
    var *= (1.f / DD);

    float z = d * rsqrtf(var + 1e-5f) * ln_g[t] + ln_b[t];
    float y2 = z / (1.f + __expf(-z));
    out[idx] = y2;
    splitbf(y2, g_h_hi[idx], g_h_lo[idx]);   // fused split for next layer's GEMMs
}

// ---------------- launch ----------------
extern "C" void kernel_launch(void* const* d_in, const int* in_sizes, int n_in,
                              void* d_out, int out_size) {
    const float* x    = (const float*)d_in[0];
    const float* lu   = (const float*)d_in[1];
    const int*   ei   = (const int*)d_in[2];
    const float* t    = (const float*)d_in[3];
    const float* msg  = (const float*)d_in[4];
    const float* wlin = (const float*)d_in[5];
    const float* blin = (const float*)d_in[6];
    const float* w    = (const float*)d_in[7];
    const float* b    = (const float*)d_in[8];
    const float* lin_w = (const float*)d_in[9];
    const float* lin_b = (const float*)d_in[10];
    const float* Wq = (const float*)d_in[11];
    const float* bq = (const float*)d_in[12];
    const float* Wk = (const float*)d_in[13];
    const float* bk = (const float*)d_in[14];
    const float* Wv = (const float*)d_in[15];
    const float* bv = (const float*)d_in[16];
    const float* We = (const float*)d_in[17];
    const float* Ws = (const float*)d_in[18];
    const float* bs = (const float*)d_in[19];
    const float* lng = (const float*)d_in[20];
    const float* lnb = (const float*)d_in[21];
    float* out = (float*)d_out;

    cudaFuncSetAttribute(k_mma, cudaFuncAttributeMaxDynamicSharedMemorySize, SMEM_MM);

    void* p;
    cudaGetSymbolAddress(&p, g_h);    float* ph = (float*)p;
    cudaGetSymbolAddress(&p, g_q);    float* pq = (float*)p;
    cudaGetSymbolAddress(&p, g_k);    float* pk = (float*)p;
    cudaGetSymbolAddress(&p, g_v);    float* pv = (float*)p;
    cudaGetSymbolAddress(&p, g_skip); float* ps = (float*)p;
    cudaGetSymbolAddress(&p, g_e);    float* pe = (float*)p;
    cudaGetSymbolAddress(&p, g_ea_hi); __nv_bfloat16* eah = (__nv_bfloat16*)p;
    cudaGetSymbolAddress(&p, g_ea_lo); __nv_bfloat16* eal = (__nv_bfloat16*)p;
    cudaGetSymbolAddress(&p, g_h_hi);  __nv_bfloat16* hhi = (__nv_bfloat16*)p;
    cudaGetSymbolAddress(&p, g_h_lo);  __nv_bfloat16* hlo = (__nv_bfloat16*)p;
    cudaGetSymbolAddress(&p, g_x_hi);  __nv_bfloat16* xhi = (__nv_bfloat16*)p;
    cudaGetSymbolAddress(&p, g_x_lo);  __nv_bfloat16* xlo = (__nv_bfloat16*)p;
    cudaGetSymbolAddress(&p, g_wn_hi); __nv_bfloat16* wnh = (__nv_bfloat16*)p;
    cudaGetSymbolAddress(&p, g_wn_lo); __nv_bfloat16* wnl = (__nv_bfloat16*)p;
    cudaGetSymbolAddress(&p, g_we_hi); __nv_bfloat16* weh = (__nv_bfloat16*)p;
    cudaGetSymbolAddress(&p, g_we_lo); __nv_bfloat16* wel = (__nv_bfloat16*)p;
    cudaGetSymbolAddress(&p, g_wl_hi); __nv_bfloat16* wlh = (__nv_bfloat16*)p;
    cudaGetSymbolAddress(&p, g_wl_lo); __nv_bfloat16* wll = (__nv_bfloat16*)p;

    // CSR build + edge attributes (split) + weight packing
    k_zero_deg<<<(NN + 255) / 256, 256>>>();
    k_count<<<(EE + 255) / 256, 256>>>(ei);
    k_scan<<<1, 1024>>>();
    k_scatter<<<(EE + 255) / 256, 256>>>(ei);
    k_edge_attr<<<(EE * 128 + 255) / 256, 256>>>(ei, lu, t, msg, wlin, blin, w, b);
    k_split_wn<<<(12 * 65536 + 255) / 256, 256>>>(Wq, Wk, Wv, Ws);
    k_split_we<<<(3 * 32768 + 255) / 256, 256>>>(We);
    k_split_wl<<<(32768 + 255) / 256, 256>>>(lin_w);
    k_split_x<<<(NN * 128 + 255) / 256, 256>>>(x);

    dim3 gn(2, (NN + 127) / 128);   // (2, 157)
    dim3 ge(2, EE / 128);           // (2, 2500)

    // input projection (K padded to 128), then one explicit h split
    k_mma<<<gn, 256, SMEM_MM>>>(xhi, xlo, wlh, wll, lin_b, ph, NN, 128);
    k_split_h<<<(NN * 256 + 255) / 256, 256>>>();

    for (int i = 0; i < LL; i++) {
        const __nv_bfloat16* wqh = wnh + (i * 4 + 0) * 65536;
        const __nv_bfloat16* wql = wnl + (i * 4 + 0) * 65536;
        const __nv_bfloat16* wkh = wnh + (i * 4 + 1) * 65536;
        const __nv_bfloat16* wkl = wnl + (i * 4 + 1) * 65536;
        const __nv_bfloat16* wvh = wnh + (i * 4 + 2) * 65536;
        const __nv_bfloat16* wvl = wnl + (i * 4 + 2) * 65536;
        const __nv_bfloat16* wsh = wnh + (i * 4 + 3) * 65536;
        const __nv_bfloat16* wsl = wnl + (i * 4 + 3) * 65536;
        k_mma<<<gn, 256, SMEM_MM>>>(hhi, hlo, wqh, wql, bq + i * DD, pq, NN, 256);
        k_mma<<<gn, 256, SMEM_MM>>>(hhi, hlo, wkh, wkl, bk + i * DD, pk, NN, 256);
        k_mma<<<gn, 256, SMEM_MM>>>(hhi, hlo, wvh, wvl, bv + i * DD, pv, NN, 256);
        k_mma<<<gn, 256, SMEM_MM>>>(hhi, hlo, wsh, wsl, bs + i * DD, ps, NN, 256);
        k_mma<<<ge, 256, SMEM_MM>>>(eah, eal, weh + i * 32768, wel + i * 32768,
                                    (const float*)nullptr, pe, EE, 128);
        k_attn<<<(NN * HH * 32 + 255) / 256, 256>>>();
        k_node_update<<<NN, DD>>>(lng + i * DD, lnb + i * DD, (i == LL - 1) ? out : ph);
    }
}

// round 10
// speedup vs baseline: 2.4007x; 1.4470x over previous
#include <cuda_runtime.h>
#include <cuda_bf16.h>
#include <math.h>
#include <stdint.h>

#define NN 20000
#define EE 320000
#define DD 256
#define HH 2
#define CC 128
#define LL 3
#define EK 96      // edge-attr K padded (real 73)

// ---------------- scratch (static __device__, no allocation) ----------------
__device__ __nv_bfloat16 g_ea_hi[EE * EK];
__device__ __nv_bfloat16 g_ea_lo[EE * EK];
__device__ __nv_bfloat16 g_h_hi[NN * 256];
__device__ __nv_bfloat16 g_h_lo[NN * 256];
__device__ __nv_bfloat16 g_x_hi[NN * 128];
__device__ __nv_bfloat16 g_x_lo[NN * 128];
__device__ __nv_bfloat16 g_wn_hi[12 * 256 * 256];  // per layer: [Wq;Wk;Wv;Ws] = [1024][256] K-major
__device__ __nv_bfloat16 g_wn_lo[12 * 256 * 256];
__device__ __nv_bfloat16 g_we_hi[3 * 256 * EK];
__device__ __nv_bfloat16 g_we_lo[3 * 256 * EK];
__device__ __nv_bfloat16 g_wl_hi[256 * 128];
__device__ __nv_bfloat16 g_wl_lo[256 * 128];

__device__ float g_h[NN * DD];
__device__ float g_q[NN * DD];
__device__ float g_k[NN * DD];
__device__ float g_v[NN * DD];
__device__ float g_skip[NN * DD];
__device__ float g_e[EE * DD];             // 328 MB
__device__ float g_aggr[NN * DD];
__device__ int   g_rowptr[NN + 1];
__device__ int   g_cursor[NN];
__device__ int   g_deg[NN];
__device__ int2  g_edge[EE];               // (eid, src) fused

__device__ __forceinline__ uint32_t smem_u32(const void* p) {
    uint32_t a;
    asm("{ .reg .u64 t; cvta.to.shared.u64 t, %1; cvt.u32.u64 %0, t; }" : "=r"(a) : "l"(p));
    return a;
}
__device__ __forceinline__ void splitbf(float x, __nv_bfloat16& h, __nv_bfloat16& l) {
    h = __float2bfloat16(x);
    l = __float2bfloat16(x - __bfloat162float(h));
}

// ---------------- CSR build ----------------
__global__ void k_zero_deg() {
    int i = blockIdx.x * blockDim.x + threadIdx.x;
    if (i < NN) g_deg[i] = 0;
}
__global__ void k_count(const int* __restrict__ ei) {
    int e = blockIdx.x * blockDim.x + threadIdx.x;
    if (e < EE) atomicAdd(&g_deg[ei[EE + e]], 1);
}
__global__ void k_scan() {
    __shared__ int sums[1024];
    const int PER = 20;
    int tid = threadIdx.x;
    int base = tid * PER;
    int local[PER];
    int s = 0;
#pragma unroll
    for (int i = 0; i < PER; i++) {
        int idx = base + i;
        int d = (idx < NN) ? g_deg[idx] : 0;
        local[i] = s;
        s += d;
    }
    sums[tid] = s;
    __syncthreads();
    for (int off = 1; off < 1024; off <<= 1) {
        int t2 = (tid >= off) ? sums[tid - off] : 0;
        __syncthreads();
        sums[tid] += t2;
        __syncthreads();
    }
    int pre = (tid > 0) ? sums[tid - 1] : 0;
#pragma unroll
    for (int i = 0; i < PER; i++) {
        int idx = base + i;
        if (idx < NN) {
            g_rowptr[idx] = pre + local[i];
            g_cursor[idx] = 0;
        }
    }
    if (tid == 1023) g_rowptr[NN] = sums[1023];
}
__global__ void k_scatter(const int* __restrict__ ei) {
    int e = blockIdx.x * blockDim.x + threadIdx.x;
    if (e < EE) {
        int d = ei[EE + e];
        int pos = g_rowptr[d] + atomicAdd(&g_cursor[d], 1);
        g_edge[pos] = make_int2(e, ei[e]);
    }
}

// ---------------- edge attributes, split bf16 hi/lo, K padded to 96 ----------------
__global__ void k_edge_attr(const int* __restrict__ ei,
                            const float* __restrict__ last_update,
                            const float* __restrict__ t,
                            const float* __restrict__ msg,
                            const float* __restrict__ wlin,
                            const float* __restrict__ blin,
                            const float* __restrict__ w,
                            const float* __restrict__ b) {
    int idx = blockIdx.x * blockDim.x + threadIdx.x;
    if (idx >= EE * EK) return;
    int e = idx / EK;
    int j = idx - e * EK;
    float v;
    if (j < 9) {
        float rel = last_update[ei[e]] - t[e];
        if (j == 0) v = rel * wlin[0] + blin[0];
        else        v = sinf(rel * w[j - 1] + b[j - 1]);
    } else if (j < 73) {
        v = msg[e * 64 + (j - 9)];
    } else {
        v = 0.f;
    }
    splitbf(v, g_ea_hi[idx], g_ea_lo[idx]);
}

// ---------------- weight / activation split kernels ----------------
__global__ void k_split_wn(const float* __restrict__ Wq, const float* __restrict__ Wk,
                           const float* __restrict__ Wv, const float* __restrict__ Ws) {
    int idx = blockIdx.x * blockDim.x + threadIdx.x;
    if (idx >= 12 * 65536) return;
    int mat = idx >> 16;
    int r = idx & 65535;
    int n = r >> 8, k = r & 255;
    int layer = mat >> 2, ty = mat & 3;
    const float* W = (ty == 0 ? Wq : ty == 1 ? Wk : ty == 2 ? Wv : Ws) + layer * 65536;
    splitbf(W[k * 256 + n], g_wn_hi[idx], g_wn_lo[idx]);
}
__global__ void k_split_we(const float* __restrict__ We) {
    int idx = blockIdx.x * blockDim.x + threadIdx.x;
    if (idx >= 3 * 256 * EK) return;
    int mat = idx / (256 * EK);
    int r = idx - mat * (256 * EK);
    int n = r / EK, k = r - n * EK;
    float v = (k < 73) ? We[mat * 73 * 256 + k * 256 + n] : 0.f;
    splitbf(v, g_we_hi[idx], g_we_lo[idx]);
}
__global__ void k_split_wl(const float* __restrict__ lin_w) {
    int idx = blockIdx.x * blockDim.x + threadIdx.x;
    if (idx >= 32768) return;
    int n = idx >> 7, k = idx & 127;
    float v = (k < 100) ? lin_w[k * 256 + n] : 0.f;
    splitbf(v, g_wl_hi[idx], g_wl_lo[idx]);
}
__global__ void k_split_x(const float* __restrict__ x) {
    int idx = blockIdx.x * blockDim.x + threadIdx.x;
    if (idx >= NN * 128) return;
    int m = idx >> 7, k = idx & 127;
    float v = (k < 100) ? x[m * 100 + k] : 0.f;
    splitbf(v, g_x_hi[idx], g_x_lo[idx]);
}
__global__ void k_split_h() {
    int idx = blockIdx.x * blockDim.x + threadIdx.x;
    if (idx >= NN * 256) return;
    splitbf(g_h[idx], g_h_hi[idx], g_h_lo[idx]);
}

// ---------------- split-bf16 mma.sync GEMM with cp.async + ldmatrix ----------------
// C[M,N] = A@B^T + bias with N up to 1024; output column block c (256-wide) routes
// to C{c} with local 256-stride (fused QKV/skip). A hi/lo [M][K]; B hi/lo [N][K].
#define LDT 40                       // smem row stride in bf16 (80 B)
#define TILE_B (128 * LDT * 2)       // 10240 B per operand tile
#define STAGE_B (4 * TILE_B)
#define SMEM_MM (2 * STAGE_B)        // 81920 B

__device__ __forceinline__ void mma16816(float* d, const uint32_t* a, const uint32_t* b) {
    asm volatile(
        "mma.sync.aligned.m16n8k16.row.col.f32.bf16.bf16.f32 "
        "{%0,%1,%2,%3},{%4,%5,%6,%7},{%8,%9},{%0,%1,%2,%3};"
        : "+f"(d[0]), "+f"(d[1]), "+f"(d[2]), "+f"(d[3])
        : "r"(a[0]), "r"(a[1]), "r"(a[2]), "r"(a[3]), "r"(b[0]), "r"(b[1]));
}
__device__ __forceinline__ void ldm4(uint32_t* r, uint32_t addr) {
    asm volatile("ldmatrix.sync.aligned.m8n8.x4.shared.b16 {%0,%1,%2,%3}, [%4];"
                 : "=r"(r[0]), "=r"(r[1]), "=r"(r[2]), "=r"(r[3]) : "r"(addr));
}
__device__ __forceinline__ void cp16(uint32_t dst, const void* src, int szr) {
    asm volatile("cp.async.cg.shared.global [%0], [%1], 16, %2;"
                 :: "r"(dst), "l"(src), "r"(szr));
}

__device__ __forceinline__ void mm_load_stage(
    uint32_t sbase, int st, int kt, int row0, int col0, int M, int K,
    const __nv_bfloat16* Ah, const __nv_bfloat16* Al,
    const __nv_bfloat16* Bh, const __nv_bfloat16* Bl, int tid) {
    int kg0 = kt * 32;
#pragma unroll
    for (int i = 0; i < 8; i++) {
        int c = tid + i * 256;
        int op = c >> 9;                       // 0:Ah 1:Al 2:Bh 3:Bl
        int r = (c >> 2) & 127, seg = c & 3;
        const __nv_bfloat16* S = (op == 0) ? Ah : (op == 1) ? Al : (op == 2) ? Bh : Bl;
        int gr = (op < 2) ? (row0 + r) : (col0 + r);
        int valid = (op < 2) ? (gr < M) : 1;
        uint32_t dst = sbase + st * STAGE_B + op * TILE_B + r * (LDT * 2) + seg * 16;
        const __nv_bfloat16* src = S + (valid ? ((size_t)gr * K + kg0 + seg * 8) : 0);
        cp16(dst, src, valid ? 16 : 0);
    }
}

__global__ __launch_bounds__(256) void k_mma(
    const __nv_bfloat16* __restrict__ Ah, const __nv_bfloat16* __restrict__ Al,
    const __nv_bfloat16* __restrict__ Bh, const __nv_bfloat16* __restrict__ Bl,
    const float* b0, const float* b1, const float* b2, const float* b3,
    float* C0, float* C1, float* C2, float* C3,
    int M, int K) {
    extern __shared__ char sm[];
    uint32_t sbase = smem_u32(sm);
    int tid = threadIdx.x, warp = tid >> 5, lane = tid & 31;
    int g = lane >> 2, tig = lane & 3;
    int wm = (warp & 1) * 64, wn = (warp >> 1) * 32;
    int row0 = blockIdx.y * 128, col0 = blockIdx.x * 128;
    int nkt = K >> 5;

    float acc[4][4][4];
#pragma unroll
    for (int mi = 0; mi < 4; mi++)
#pragma unroll
        for (int ni = 0; ni < 4; ni++)
#pragma unroll
            for (int r = 0; r < 4; r++) acc[mi][ni][r] = 0.f;

    mm_load_stage(sbase, 0, 0, row0, col0, M, K, Ah, Al, Bh, Bl, tid);
    asm volatile("cp.async.commit_group;");

    for (int kt = 0; kt < nkt; kt++) {
        if (kt + 1 < nkt) {
            mm_load_stage(sbase, (kt + 1) & 1, kt + 1, row0, col0, M, K, Ah, Al, Bh, Bl, tid);
            asm volatile("cp.async.commit_group;");
            asm volatile("cp.async.wait_group 1;");
        } else {
            asm volatile("cp.async.wait_group 0;");
        }
        __syncthreads();

        uint32_t at  = sbase + (kt & 1) * STAGE_B;
        uint32_t alt = at + TILE_B;
        uint32_t bt  = at + 2 * TILE_B;
        uint32_t blt = at + 3 * TILE_B;
        int arow = (lane & 15);
        int acol = (lane >> 4) * 8;
#pragma unroll
        for (int ks = 0; ks < 32; ks += 16) {
            uint32_t rah[4][4], ral[4][4], rbh[4][2], rbl[4][2];
#pragma unroll
            for (int mi = 0; mi < 4; mi++) {
                uint32_t off = ((wm + mi * 16 + arow) * LDT + ks + acol) * 2;
                ldm4(rah[mi], at + off);
                ldm4(ral[mi], alt + off);
            }
#pragma unroll
            for (int ni = 0; ni < 4; ni++) {
                uint32_t off = ((wn + ni * 8 + g) * LDT + ks + 2 * tig) * 2;
                rbh[ni][0] = *(const uint32_t*)(sm + (bt - sbase) + off);
                rbh[ni][1] = *(const uint32_t*)(sm + (bt - sbase) + off + 16);
                rbl[ni][0] = *(const uint32_t*)(sm + (blt - sbase) + off);
                rbl[ni][1] = *(const uint32_t*)(sm + (blt - sbase) + off + 16);
            }
#pragma unroll
            for (int mi = 0; mi < 4; mi++)
#pragma unroll
                for (int ni = 0; ni < 4; ni++) {
                    mma16816(acc[mi][ni], rah[mi], rbh[ni]);
                    mma16816(acc[mi][ni], rah[mi], rbl[ni]);
                    mma16816(acc[mi][ni], ral[mi], rbh[ni]);
                }
        }
        __syncthreads();
    }

    // epilogue: route 256-wide column block, add bias, store
    int cb = col0 >> 8;
    float* C = (cb == 0) ? C0 : (cb == 1) ? C1 : (cb == 2) ? C2 : C3;
    const float* bias = (cb == 0) ? b0 : (cb == 1) ? b1 : (cb == 2) ? b2 : b3;
    int coll0 = col0 & 255;
#pragma unroll
    for (int ni = 0; ni < 4; ni++) {
        int col = coll0 + wn + ni * 8 + 2 * tig;
        float2 bz = make_float2(0.f, 0.f);
        if (bias) bz = *(const float2*)(bias + col);
#pragma unroll
        for (int mi = 0; mi < 4; mi++) {
            int r = row0 + wm + mi * 16 + g;
            if (r < M) {
                float2 o = make_float2(acc[mi][ni][0] + bz.x, acc[mi][ni][1] + bz.y);
                *(float2*)(C + (size_t)r * 256 + col) = o;
            }
            if (r + 8 < M) {
                float2 o = make_float2(acc[mi][ni][2] + bz.x, acc[mi][ni][3] + bz.y);
                *(float2*)(C + (size_t)(r + 8) * 256 + col) = o;
            }
        }
    }
}

// ---------------- attention: one warp per (node, head), unroll 2 ----------------
__global__ void k_attn() {
    int gw = (blockIdx.x * blockDim.x + threadIdx.x) >> 5;
    int lane = threadIdx.x & 31;
    if (gw >= NN * HH) return;
    int n = gw >> 1, h = gw & 1;
    int base = n * DD + h * CC + lane * 4;
    float4 q4 = *(const float4*)(g_q + base);
    int beg = g_rowptr[n], end = g_rowptr[n + 1];
    float m = -3.4e38f, l = 0.f;
    float ax = 0.f, ay = 0.f, az = 0.f, aw = 0.f;
    const float scale = 0.0883883476483184406f;  // 1/sqrt(128)
    int hoff = h * CC + lane * 4;

    int i = beg;
    for (; i + 2 <= end; i += 2) {
        int2 ed0 = g_edge[i];
        int2 ed1 = g_edge[i + 1];
        const float4 e0 = *(const float4*)(g_e + (size_t)ed0.x * DD + hoff);
        const float4 k0 = *(const float4*)(g_k + (size_t)ed0.y * DD + hoff);
        const float4 v0 = *(const float4*)(g_v + (size_t)ed0.y * DD + hoff);
        const float4 e1 = *(const float4*)(g_e + (size_t)ed1.x * DD + hoff);
        const float4 k1 = *(const float4*)(g_k + (size_t)ed1.y * DD + hoff);
        const float4 v1 = *(const float4*)(g_v + (size_t)ed1.y * DD + hoff);
        float p0 = q4.x * (k0.x + e0.x) + q4.y * (k0.y + e0.y) +
                   q4.z * (k0.z + e0.z) + q4.w * (k0.w + e0.w);
        float p1 = q4.x * (k1.x + e1.x) + q4.y * (k1.y + e1.y) +
                   q4.z * (k1.z + e1.z) + q4.w * (k1.w + e1.w);
#pragma unroll
        for (int off = 16; off; off >>= 1) {
            p0 += __shfl_xor_sync(0xffffffffu, p0, off);
            p1 += __shfl_xor_sync(0xffffffffu, p1, off);
        }
        float a0 = p0 * scale, a1 = p1 * scale;
        float mnew = fmaxf(m, fmaxf(a0, a1));
        float corr = __expf(m - mnew);
        float w0 = __expf(a0 - mnew);
        float w1 = __expf(a1 - mnew);
        l = l * corr + w0 + w1;
        ax = ax * corr + w0 * (v0.x + e0.x) + w1 * (v1.x + e1.x);
        ay = ay * corr + w0 * (v0.y + e0.y) + w1 * (v1.y + e1.y);
        az = az * corr + w0 * (v0.z + e0.z) + w1 * (v1.z + e1.z);
        aw = aw * corr + w0 * (v0.w + e0.w) + w1 * (v1.w + e1.w);
        m = mnew;
    }
    for (; i < end; i++) {
        int2 ed = g_edge[i];
        const float4 e4 = *(const float4*)(g_e + (size_t)ed.x * DD + hoff);
        const float4 k4 = *(const float4*)(g_k + (size_t)ed.y * DD + hoff);
        const float4 v4 = *(const float4*)(g_v + (size_t)ed.y * DD + hoff);
        float part = q4.x * (k4.x + e4.x) + q4.y * (k4.y + e4.y) +
                     q4.z * (k4.z + e4.z) + q4.w * (k4.w + e4.w);
#pragma unroll
        for (int off = 16; off; off >>= 1)
            part += __shfl_xor_sync(0xffffffffu, part, off);
        float alpha = part * scale;
        float mnew = fmaxf(m, alpha);
        float corr = __expf(m - mnew);
        float p = __expf(alpha - mnew);
        l = l * corr + p;
        ax = ax * corr + p * (v4.x + e4.x);
        ay = ay * corr + p * (v4.y + e4.y);
        az = az * corr + p * (v4.z + e4.z);
        aw = aw * corr + p * (v4.w + e4.w);
        m = mnew;
    }
    float inv = (l > 0.f) ? 1.f / l : 0.f;
    float4 o = {ax * inv, ay * inv, az * inv, aw * inv};
    *(float4*)(g_aggr + base) = o;
}

// ---------------- residual + layernorm + silu (+ fused bf16 split of new h) ----------------
__global__ void k_node_update(const float* __restrict__ ln_g,
                              const float* __restrict__ ln_b,
                              float* __restrict__ out) {
    int n = blockIdx.x, t = threadIdx.x;
    int idx = n * DD + t;
    float y = g_h[idx] + g_aggr[idx] + g_skip[idx];
    __shared__ float red[8];
    int w = t >> 5, lane = t & 31;

    float s = y;
#pragma unroll
    for (int off = 16; off; off >>= 1) s += __shfl_xor_sync(0xffffffffu, s, off);
    if (lane == 0) red[w] = s;
    __syncthreads();
    float mu = 0.f;
#pragma unroll
    for (int i = 0; i < 8; i++) mu += red[i];
    mu *= (1.f / DD);

    float d = y - mu;
    float s2 = d * d;
#pragma unroll
    for (int off = 16; off; off >>= 1) s2 += __shfl_xor_sync(0xffffffffu, s2, off);
    __syncthreads();
    if (lane == 0) red[w] = s2;
    __syncthreads();
    float var = 0.f;
#pragma unroll
    for (int i = 0; i < 8; i++) var += red[i];
    var *= (1.f / DD);

    float z = d * rsqrtf(var + 1e-5f) * ln_g[t] + ln_b[t];
    float y2 = z / (1.f + __expf(-z));
    out[idx] = y2;
    splitbf(y2, g_h_hi[idx], g_h_lo[idx]);
}

// ---------------- launch ----------------
extern "C" void kernel_launch(void* const* d_in, const int* in_sizes, int n_in,
                              void* d_out, int out_size) {
    const float* x    = (const float*)d_in[0];
    const float* lu   = (const float*)d_in[1];
    const int*   ei   = (const int*)d_in[2];
    const float* t    = (const float*)d_in[3];
    const float* msg  = (const float*)d_in[4];
    const float* wlin = (const float*)d_in[5];
    const float* blin = (const float*)d_in[6];
    const float* w    = (const float*)d_in[7];
    const float* b    = (const float*)d_in[8];
    const float* lin_w = (const float*)d_in[9];
    const float* lin_b = (const float*)d_in[10];
    const float* Wq = (const float*)d_in[11];
    const float* bq = (const float*)d_in[12];
    const float* Wk = (const float*)d_in[13];
    const float* bk = (const float*)d_in[14];
    const float* Wv = (const float*)d_in[15];
    const float* bv = (const float*)d_in[16];
    const float* We = (const float*)d_in[17];
    const float* Ws = (const float*)d_in[18];
    const float* bs = (const float*)d_in[19];
    const float* lng = (const float*)d_in[20];
    const float* lnb = (const float*)d_in[21];
    float* out = (float*)d_out;

    cudaFuncSetAttribute(k_mma, cudaFuncAttributeMaxDynamicSharedMemorySize, SMEM_MM);

    void* p;
    cudaGetSymbolAddress(&p, g_h);    float* ph = (float*)p;
    cudaGetSymbolAddress(&p, g_q);    float* pq = (float*)p;
    cudaGetSymbolAddress(&p, g_k);    float* pk = (float*)p;
    cudaGetSymbolAddress(&p, g_v);    float* pv = (float*)p;
    cudaGetSymbolAddress(&p, g_skip); float* ps = (float*)p;
    cudaGetSymbolAddress(&p, g_e);    float* pe = (float*)p;
    cudaGetSymbolAddress(&p, g_ea_hi); __nv_bfloat16* eah = (__nv_bfloat16*)p;
    cudaGetSymbolAddress(&p, g_ea_lo); __nv_bfloat16* eal = (__nv_bfloat16*)p;
    cudaGetSymbolAddress(&p, g_h_hi);  __nv_bfloat16* hhi = (__nv_bfloat16*)p;
    cudaGetSymbolAddress(&p, g_h_lo);  __nv_bfloat16* hlo = (__nv_bfloat16*)p;
    cudaGetSymbolAddress(&p, g_x_hi);  __nv_bfloat16* xhi = (__nv_bfloat16*)p;
    cudaGetSymbolAddress(&p, g_x_lo);  __nv_bfloat16* xlo = (__nv_bfloat16*)p;
    cudaGetSymbolAddress(&p, g_wn_hi); __nv_bfloat16* wnh = (__nv_bfloat16*)p;
    cudaGetSymbolAddress(&p, g_wn_lo); __nv_bfloat16* wnl = (__nv_bfloat16*)p;
    cudaGetSymbolAddress(&p, g_we_hi); __nv_bfloat16* weh = (__nv_bfloat16*)p;
    cudaGetSymbolAddress(&p, g_we_lo); __nv_bfloat16* wel = (__nv_bfloat16*)p;
    cudaGetSymbolAddress(&p, g_wl_hi); __nv_bfloat16* wlh = (__nv_bfloat16*)p;
    cudaGetSymbolAddress(&p, g_wl_lo); __nv_bfloat16* wll = (__nv_bfloat16*)p;

    // CSR build + edge attributes (split) + weight packing
    k_zero_deg<<<(NN + 255) / 256, 256>>>();
    k_count<<<(EE + 255) / 256, 256>>>(ei);
    k_scan<<<1, 1024>>>();
    k_scatter<<<(EE + 255) / 256, 256>>>(ei);
    k_edge_attr<<<(EE * EK + 255) / 256, 256>>>(ei, lu, t, msg, wlin, blin, w, b);
    k_split_wn<<<(12 * 65536 + 255) / 256, 256>>>(Wq, Wk, Wv, Ws);
    k_split_we<<<(3 * 256 * EK + 255) / 256, 256>>>(We);
    k_split_wl<<<(32768 + 255) / 256, 256>>>(lin_w);
    k_split_x<<<(NN * 128 + 255) / 256, 256>>>(x);

    dim3 gin(2, (NN + 127) / 128);   // input proj: N=256
    dim3 gqkvs(8, (NN + 127) / 128); // fused node GEMM: N=1024
    dim3 ge(2, EE / 128);            // edge GEMM: N=256

    // input projection (K padded to 128), then one explicit h split
    k_mma<<<gin, 256, SMEM_MM>>>(xhi, xlo, wlh, wll,
                                 lin_b, lin_b, lin_b, lin_b,
                                 ph, ph, ph, ph, NN, 128);
    k_split_h<<<(NN * 256 + 255) / 256, 256>>>();

    for (int i = 0; i < LL; i++) {
        // fused Q|K|V|skip: B = [1024][256] contiguous block for this layer
        k_mma<<<gqkvs, 256, SMEM_MM>>>(hhi, hlo,
                                       wnh + i * 4 * 65536, wnl + i * 4 * 65536,
                                       bq + i * DD, bk + i * DD, bv + i * DD, bs + i * DD,
                                       pq, pk, pv, ps, NN, 256);
        k_mma<<<ge, 256, SMEM_MM>>>(eah, eal,
                                    weh + i * 256 * EK, wel + i * 256 * EK,
                                    (const float*)nullptr, (const float*)nullptr,
                                    (const float*)nullptr, (const float*)nullptr,
                                    pe, pe, pe, pe, EE, EK);
        k_attn<<<(NN * HH * 32 + 255) / 256, 256>>>();
        k_node_update<<<NN, DD>>>(lng + i * DD, lnb + i * DD, (i == LL - 1) ? out : ph);
    }
}

// round 12
// speedup vs baseline: 3.0322x; 1.2630x over previous
#include <cuda_runtime.h>
#include <cuda_bf16.h>
#include <math.h>
#include <stdint.h>

#define NN 20000
#define EE 320000
#define DD 256
#define HH 2
#define CC 128
#define LL 3
#define EK 96      // edge-attr dim padded (real 73)

// ---------------- scratch (static __device__, no allocation) ----------------
__device__ float g_ea[EE * EK];                    // fp32 edge attrs, zero-padded (123 MB)
__device__ __nv_bfloat16 g_h_hi[NN * 256];
__device__ __nv_bfloat16 g_h_lo[NN * 256];
__device__ __nv_bfloat16 g_x_hi[NN * 128];
__device__ __nv_bfloat16 g_x_lo[NN * 128];
__device__ __nv_bfloat16 g_wn_hi[3 * 1280 * 256];  // per layer rows: Wq|Wk|Wv|Ws|Wc (K-major)
__device__ __nv_bfloat16 g_wn_lo[3 * 1280 * 256];
__device__ __nv_bfloat16 g_we_hi[3 * 256 * EK];    // We [out ch][edge dim]
__device__ __nv_bfloat16 g_we_lo[3 * 256 * EK];
__device__ __nv_bfloat16 g_wl_hi[256 * 128];
__device__ __nv_bfloat16 g_wl_lo[256 * 128];
__device__ __nv_bfloat16 g_as_hi[HH * NN * EK];    // softmax-weighted edge-attr sums
__device__ __nv_bfloat16 g_as_lo[HH * NN * EK];
__device__ float g_bz[3 * 256];                    // bias of z block

__device__ float g_h[NN * DD];
__device__ float g_q[NN * DD];
__device__ float g_k[NN * DD];
__device__ float g_v[NN * DD];
__device__ float g_skip[NN * DD];
__device__ float g_z[NN * DD];                     // z = We^T q, per head 128-col block
__device__ float g_aggr[NN * DD];
__device__ float g_ag2[NN * DD];                   // e-contribution to aggregation
__device__ int   g_rowptr[NN + 1];
__device__ int   g_cursor[NN];
__device__ int   g_deg[NN];
__device__ int2  g_edge[EE];                       // (eid, src)

__device__ __forceinline__ uint32_t smem_u32(const void* p) {
    uint32_t a;
    asm("{ .reg .u64 t; cvta.to.shared.u64 t, %1; cvt.u32.u64 %0, t; }" : "=r"(a) : "l"(p));
    return a;
}
__device__ __forceinline__ void splitbf(float x, __nv_bfloat16& h, __nv_bfloat16& l) {
    h = __float2bfloat16(x);
    l = __float2bfloat16(x - __bfloat162float(h));
}

// ---------------- CSR build ----------------
__global__ void k_zero_deg() {
    int i = blockIdx.x * blockDim.x + threadIdx.x;
    if (i < NN) g_deg[i] = 0;
}
__global__ void k_count(const int* __restrict__ ei) {
    int e = blockIdx.x * blockDim.x + threadIdx.x;
    if (e < EE) atomicAdd(&g_deg[ei[EE + e]], 1);
}
__global__ void k_scan() {
    __shared__ int sums[1024];
    const int PER = 20;
    int tid = threadIdx.x;
    int base = tid * PER;
    int local[PER];
    int s = 0;
#pragma unroll
    for (int i = 0; i < PER; i++) {
        int idx = base + i;
        int d = (idx < NN) ? g_deg[idx] : 0;
        local[i] = s;
        s += d;
    }
    sums[tid] = s;
    __syncthreads();
    for (int off = 1; off < 1024; off <<= 1) {
        int t2 = (tid >= off) ? sums[tid - off] : 0;
        __syncthreads();
        sums[tid] += t2;
        __syncthreads();
    }
    int pre = (tid > 0) ? sums[tid - 1] : 0;
#pragma unroll
    for (int i = 0; i < PER; i++) {
        int idx = base + i;
        if (idx < NN) {
            g_rowptr[idx] = pre + local[i];
            g_cursor[idx] = 0;
        }
    }
    if (tid == 1023) g_rowptr[NN] = sums[1023];
}
__global__ void k_scatter(const int* __restrict__ ei) {
    int e = blockIdx.x * blockDim.x + threadIdx.x;
    if (e < EE) {
        int d = ei[EE + e];
        int pos = g_rowptr[d] + atomicAdd(&g_cursor[d], 1);
        g_edge[pos] = make_int2(e, ei[e]);
    }
}

// ---------------- edge attributes (fp32, zero pad to 96) ----------------
__global__ void k_edge_attr(const int* __restrict__ ei,
                            const float* __restrict__ last_update,
                            const float* __restrict__ t,
                            const float* __restrict__ msg,
                            const float* __restrict__ wlin,
                            const float* __restrict__ blin,
                            const float* __restrict__ w,
                            const float* __restrict__ b) {
    int idx = blockIdx.x * blockDim.x + threadIdx.x;
    if (idx >= EE * EK) return;
    int e = idx / EK;
    int j = idx - e * EK;
    float v;
    if (j < 9) {
        float rel = last_update[ei[e]] - t[e];
        if (j == 0) v = rel * wlin[0] + blin[0];
        else        v = sinf(rel * w[j - 1] + b[j - 1]);
    } else if (j < 73) {
        v = msg[e * 64 + (j - 9)];
    } else {
        v = 0.f;
    }
    g_ea[idx] = v;
}

// ---------------- weight packing ----------------
__global__ void k_split_wn(const float* __restrict__ Wq, const float* __restrict__ Wk,
                           const float* __restrict__ Wv, const float* __restrict__ Ws) {
    int idx = blockIdx.x * blockDim.x + threadIdx.x;
    if (idx >= 12 * 65536) return;
    int mat = idx >> 16;
    int r = idx & 65535;
    int n = r >> 8, k = r & 255;
    int layer = mat >> 2, ty = mat & 3;
    const float* W = (ty == 0 ? Wq : ty == 1 ? Wk : ty == 2 ? Wv : Ws) + layer * 65536;
    int dst = layer * 1280 * 256 + (ty * 256 + n) * 256 + k;
    splitbf(W[k * 256 + n], g_wn_hi[dst], g_wn_lo[dst]);
}
// composite Wc rows (1024..1279): Wc[k][c=h*128+j] = sum_m Wq[k][h*128+m]*We[j][h*128+m]
__global__ void k_wc(const float* __restrict__ Wq, const float* __restrict__ We) {
    int idx = blockIdx.x * blockDim.x + threadIdx.x;
    if (idx >= 3 * 65536) return;
    int layer = idx >> 16;
    int o = idx & 65535;
    int c = o >> 8, k = o & 255;
    int hh = c >> 7, j = c & 127;
    float s = 0.f;
    if (j < 73) {
        const float* wq = Wq + layer * 65536 + k * 256 + hh * 128;
        const float* we = We + layer * 73 * 256 + j * 256 + hh * 128;
#pragma unroll 8
        for (int m = 0; m < 128; m++) s += wq[m] * we[m];
    }
    int dst = layer * 1280 * 256 + (1024 + c) * 256 + k;
    splitbf(s, g_wn_hi[dst], g_wn_lo[dst]);
}
__global__ void k_bz(const float* __restrict__ bq, const float* __restrict__ We) {
    int idx = blockIdx.x * blockDim.x + threadIdx.x;
    if (idx >= 3 * 256) return;
    int layer = idx >> 8, c = idx & 255;
    int hh = c >> 7, j = c & 127;
    float s = 0.f;
    if (j < 73) {
        const float* bqp = bq + layer * 256 + hh * 128;
        const float* we = We + layer * 73 * 256 + j * 256 + hh * 128;
#pragma unroll 8
        for (int m = 0; m < 128; m++) s += bqp[m] * we[m];
    }
    g_bz[idx] = s;
}
__global__ void k_split_we(const float* __restrict__ We) {
    int idx = blockIdx.x * blockDim.x + threadIdx.x;
    if (idx >= 3 * 256 * EK) return;
    int mat = idx / (256 * EK);
    int r = idx - mat * (256 * EK);
    int n = r / EK, k = r - n * EK;
    float v = (k < 73) ? We[mat * 73 * 256 + k * 256 + n] : 0.f;
    splitbf(v, g_we_hi[idx], g_we_lo[idx]);
}
__global__ void k_split_wl(const float* __restrict__ lin_w) {
    int idx = blockIdx.x * blockDim.x + threadIdx.x;
    if (idx >= 32768) return;
    int n = idx >> 7, k = idx & 127;
    float v = (k < 100) ? lin_w[k * 256 + n] : 0.f;
    splitbf(v, g_wl_hi[idx], g_wl_lo[idx]);
}
__global__ void k_split_x(const float* __restrict__ x) {
    int idx = blockIdx.x * blockDim.x + threadIdx.x;
    if (idx >= NN * 128) return;
    int m = idx >> 7, k = idx & 127;
    float v = (k < 100) ? x[m * 100 + k] : 0.f;
    splitbf(v, g_x_hi[idx], g_x_lo[idx]);
}
__global__ void k_split_h() {
    int idx = blockIdx.x * blockDim.x + threadIdx.x;
    if (idx >= NN * 256) return;
    splitbf(g_h[idx], g_h_hi[idx], g_h_lo[idx]);
}

// ---------------- split-bf16 mma.sync GEMM (cp.async + ldmatrix), 5 output blocks ----------------
#define LDT 40
#define TILE_B (128 * LDT * 2)
#define STAGE_B (4 * TILE_B)
#define SMEM_MM (2 * STAGE_B)

__device__ __forceinline__ void mma16816(float* d, const uint32_t* a, const uint32_t* b) {
    asm volatile(
        "mma.sync.aligned.m16n8k16.row.col.f32.bf16.bf16.f32 "
        "{%0,%1,%2,%3},{%4,%5,%6,%7},{%8,%9},{%0,%1,%2,%3};"
        : "+f"(d[0]), "+f"(d[1]), "+f"(d[2]), "+f"(d[3])
        : "r"(a[0]), "r"(a[1]), "r"(a[2]), "r"(a[3]), "r"(b[0]), "r"(b[1]));
}
__device__ __forceinline__ void ldm4(uint32_t* r, uint32_t addr) {
    asm volatile("ldmatrix.sync.aligned.m8n8.x4.shared.b16 {%0,%1,%2,%3}, [%4];"
                 : "=r"(r[0]), "=r"(r[1]), "=r"(r[2]), "=r"(r[3]) : "r"(addr));
}
__device__ __forceinline__ void cp16(uint32_t dst, const void* src, int szr) {
    asm volatile("cp.async.cg.shared.global [%0], [%1], 16, %2;"
                 :: "r"(dst), "l"(src), "r"(szr));
}

__device__ __forceinline__ void mm_load_stage(
    uint32_t sbase, int st, int kt, int row0, int col0, int M, int K,
    const __nv_bfloat16* Ah, const __nv_bfloat16* Al,
    const __nv_bfloat16* Bh, const __nv_bfloat16* Bl, int tid) {
    int kg0 = kt * 32;
#pragma unroll
    for (int i = 0; i < 8; i++) {
        int c = tid + i * 256;
        int op = c >> 9;
        int r = (c >> 2) & 127, seg = c & 3;
        const __nv_bfloat16* S = (op == 0) ? Ah : (op == 1) ? Al : (op == 2) ? Bh : Bl;
        int gr = (op < 2) ? (row0 + r) : (col0 + r);
        int valid = (op < 2) ? (gr < M) : 1;
        uint32_t dst = sbase + st * STAGE_B + op * TILE_B + r * (LDT * 2) + seg * 16;
        const __nv_bfloat16* src = S + (valid ? ((size_t)gr * K + kg0 + seg * 8) : 0);
        cp16(dst, src, valid ? 16 : 0);
    }
}

__global__ __launch_bounds__(256) void k_mma(
    const __nv_bfloat16* __restrict__ Ah, const __nv_bfloat16* __restrict__ Al,
    const __nv_bfloat16* __restrict__ Bh, const __nv_bfloat16* __restrict__ Bl,
    const float* b0, const float* b1, const float* b2, const float* b3, const float* b4,
    float* C0, float* C1, float* C2, float* C3, float* C4,
    int M, int K) {
    extern __shared__ char sm[];
    uint32_t sbase = smem_u32(sm);
    int tid = threadIdx.x, warp = tid >> 5, lane = tid & 31;
    int g = lane >> 2, tig = lane & 3;
    int wm = (warp & 1) * 64, wn = (warp >> 1) * 32;
    int row0 = blockIdx.y * 128, col0 = blockIdx.x * 128;
    int nkt = K >> 5;

    float acc[4][4][4];
#pragma unroll
    for (int mi = 0; mi < 4; mi++)
#pragma unroll
        for (int ni = 0; ni < 4; ni++)
#pragma unroll
            for (int r = 0; r < 4; r++) acc[mi][ni][r] = 0.f;

    mm_load_stage(sbase, 0, 0, row0, col0, M, K, Ah, Al, Bh, Bl, tid);
    asm volatile("cp.async.commit_group;");

    for (int kt = 0; kt < nkt; kt++) {
        if (kt + 1 < nkt) {
            mm_load_stage(sbase, (kt + 1) & 1, kt + 1, row0, col0, M, K, Ah, Al, Bh, Bl, tid);
            asm volatile("cp.async.commit_group;");
            asm volatile("cp.async.wait_group 1;");
        } else {
            asm volatile("cp.async.wait_group 0;");
        }
        __syncthreads();

        uint32_t at  = sbase + (kt & 1) * STAGE_B;
        uint32_t alt = at + TILE_B;
        uint32_t bt  = at + 2 * TILE_B;
        uint32_t blt = at + 3 * TILE_B;
        int arow = (lane & 15);
        int acol = (lane >> 4) * 8;
#pragma unroll
        for (int ks = 0; ks < 32; ks += 16) {
            uint32_t rah[4][4], ral[4][4], rbh[4][2], rbl[4][2];
#pragma unroll
            for (int mi = 0; mi < 4; mi++) {
                uint32_t off = ((wm + mi * 16 + arow) * LDT + ks + acol) * 2;
                ldm4(rah[mi], at + off);
                ldm4(ral[mi], alt + off);
            }
#pragma unroll
            for (int ni = 0; ni < 4; ni++) {
                uint32_t off = ((wn + ni * 8 + g) * LDT + ks + 2 * tig) * 2;
                rbh[ni][0] = *(const uint32_t*)(sm + (bt - sbase) + off);
                rbh[ni][1] = *(const uint32_t*)(sm + (bt - sbase) + off + 16);
                rbl[ni][0] = *(const uint32_t*)(sm + (blt - sbase) + off);
                rbl[ni][1] = *(const uint32_t*)(sm + (blt - sbase) + off + 16);
            }
#pragma unroll
            for (int mi = 0; mi < 4; mi++)
#pragma unroll
                for (int ni = 0; ni < 4; ni++) {
                    mma16816(acc[mi][ni], rah[mi], rbh[ni]);
                    mma16816(acc[mi][ni], rah[mi], rbl[ni]);
                    mma16816(acc[mi][ni], ral[mi], rbh[ni]);
                }
        }
        __syncthreads();
    }

    int cb = col0 >> 8;
    float* C = (cb == 0) ? C0 : (cb == 1) ? C1 : (cb == 2) ? C2 : (cb == 3) ? C3 : C4;
    const float* bias = (cb == 0) ? b0 : (cb == 1) ? b1 : (cb == 2) ? b2 : (cb == 3) ? b3 : b4;
    int coll0 = col0 & 255;
#pragma unroll
    for (int ni = 0; ni < 4; ni++) {
        int col = coll0 + wn + ni * 8 + 2 * tig;
        float2 bz = make_float2(0.f, 0.f);
        if (bias) bz = *(const float2*)(bias + col);
#pragma unroll
        for (int mi = 0; mi < 4; mi++) {
            int r = row0 + wm + mi * 16 + g;
            if (r < M) {
                float2 o = make_float2(acc[mi][ni][0] + bz.x, acc[mi][ni][1] + bz.y);
                *(float2*)(C + (size_t)r * 256 + col) = o;
            }
            if (r + 8 < M) {
                float2 o = make_float2(acc[mi][ni][2] + bz.x, acc[mi][ni][3] + bz.y);
                *(float2*)(C + (size_t)(r + 8) * 256 + col) = o;
            }
        }
    }
}

// ---------------- attention: warp per (node, head); alpha = q·k + z·ea ----------------
__global__ void k_attn() {
    int gw = (blockIdx.x * blockDim.x + threadIdx.x) >> 5;
    int lane = threadIdx.x & 31;
    if (gw >= NN * HH) return;
    int n = gw >> 1, h = gw & 1;
    int hoff = h * CC + lane * 4;
    int base = n * DD + hoff;
    float4 q4 = *(const float4*)(g_q + base);
    bool eal = (lane < 24);
    float4 z4 = make_float4(0.f, 0.f, 0.f, 0.f);
    if (eal) z4 = *(const float4*)(g_z + base);
    int beg = g_rowptr[n], end = g_rowptr[n + 1];
    float m = -3.4e38f, l = 0.f;
    float ax = 0.f, ay = 0.f, az = 0.f, aw = 0.f;
    float sx = 0.f, sy = 0.f, sz = 0.f, sw = 0.f;
    const float scale = 0.0883883476483184406f;  // 1/sqrt(128)

    int i = beg;
    for (; i + 2 <= end; i += 2) {
        int2 ed0 = g_edge[i];
        int2 ed1 = g_edge[i + 1];
        float4 ea0 = make_float4(0.f, 0.f, 0.f, 0.f), ea1 = ea0;
        if (eal) {
            ea0 = *(const float4*)(g_ea + (size_t)ed0.x * EK + lane * 4);
            ea1 = *(const float4*)(g_ea + (size_t)ed1.x * EK + lane * 4);
        }
        const float4 k0 = *(const float4*)(g_k + (size_t)ed0.y * DD + hoff);
        const float4 v0 = *(const float4*)(g_v + (size_t)ed0.y * DD + hoff);
        const float4 k1 = *(const float4*)(g_k + (size_t)ed1.y * DD + hoff);
        const float4 v1 = *(const float4*)(g_v + (size_t)ed1.y * DD + hoff);
        float p0 = q4.x * k0.x + q4.y * k0.y + q4.z * k0.z + q4.w * k0.w +
                   z4.x * ea0.x + z4.y * ea0.y + z4.z * ea0.z + z4.w * ea0.w;
        float p1 = q4.x * k1.x + q4.y * k1.y + q4.z * k1.z + q4.w * k1.w +
                   z4.x * ea1.x + z4.y * ea1.y + z4.z * ea1.z + z4.w * ea1.w;
#pragma unroll
        for (int off = 16; off; off >>= 1) {
            p0 += __shfl_xor_sync(0xffffffffu, p0, off);
            p1 += __shfl_xor_sync(0xffffffffu, p1, off);
        }
        float a0 = p0 * scale, a1 = p1 * scale;
        float mnew = fmaxf(m, fmaxf(a0, a1));
        float corr = __expf(m - mnew);
        float w0 = __expf(a0 - mnew);
        float w1 = __expf(a1 - mnew);
        l = l * corr + w0 + w1;
        ax = ax * corr + w0 * v0.x + w1 * v1.x;
        ay = ay * corr + w0 * v0.y + w1 * v1.y;
        az = az * corr + w0 * v0.z + w1 * v1.z;
        aw = aw * corr + w0 * v0.w + w1 * v1.w;
        sx = sx * corr + w0 * ea0.x + w1 * ea1.x;
        sy = sy * corr + w0 * ea0.y + w1 * ea1.y;
        sz = sz * corr + w0 * ea0.z + w1 * ea1.z;
        sw = sw * corr + w0 * ea0.w + w1 * ea1.w;
        m = mnew;
    }
    for (; i < end; i++) {
        int2 ed = g_edge[i];
        float4 ea0 = make_float4(0.f, 0.f, 0.f, 0.f);
        if (eal) ea0 = *(const float4*)(g_ea + (size_t)ed.x * EK + lane * 4);
        const float4 k0 = *(const float4*)(g_k + (size_t)ed.y * DD + hoff);
        const float4 v0 = *(const float4*)(g_v + (size_t)ed.y * DD + hoff);
        float p0 = q4.x * k0.x + q4.y * k0.y + q4.z * k0.z + q4.w * k0.w +
                   z4.x * ea0.x + z4.y * ea0.y + z4.z * ea0.z + z4.w * ea0.w;
#pragma unroll
        for (int off = 16; off; off >>= 1)
            p0 += __shfl_xor_sync(0xffffffffu, p0, off);
        float a0 = p0 * scale;
        float mnew = fmaxf(m, a0);
        float corr = __expf(m - mnew);
        float w0 = __expf(a0 - mnew);
        l = l * corr + w0;
        ax = ax * corr + w0 * v0.x;
        ay = ay * corr + w0 * v0.y;
        az = az * corr + w0 * v0.z;
        aw = aw * corr + w0 * v0.w;
        sx = sx * corr + w0 * ea0.x;
        sy = sy * corr + w0 * ea0.y;
        sz = sz * corr + w0 * ea0.z;
        sw = sw * corr + w0 * ea0.w;
        m = mnew;
    }
    float inv = (l > 0.f) ? 1.f / l : 0.f;
    float4 o = {ax * inv, ay * inv, az * inv, aw * inv};
    *(float4*)(g_aggr + base) = o;
    if (eal) {
        int ai = h * (NN * EK) + n * EK + lane * 4;
        splitbf(sx * inv, g_as_hi[ai + 0], g_as_lo[ai + 0]);
        splitbf(sy * inv, g_as_hi[ai + 1], g_as_lo[ai + 1]);
        splitbf(sz * inv, g_as_hi[ai + 2], g_as_lo[ai + 2]);
        splitbf(sw * inv, g_as_hi[ai + 3], g_as_lo[ai + 3]);
    }
}

// ---------------- residual + layernorm + silu (+ fused bf16 split of new h) ----------------
__global__ void k_node_update(const float* __restrict__ ln_g,
                              const float* __restrict__ ln_b,
                              float* __restrict__ out) {
    int n = blockIdx.x, t = threadIdx.x;
    int idx = n * DD + t;
    float y = g_h[idx] + g_aggr[idx] + g_ag2[idx] + g_skip[idx];
    __shared__ float red[8];
    int w = t >> 5, lane = t & 31;

    float s = y;
#pragma unroll
    for (int off = 16; off; off >>= 1) s += __shfl_xor_sync(0xffffffffu, s, off);
    if (lane == 0) red[w] = s;
    __syncthreads();
    float mu = 0.f;
#pragma unroll
    for (int i = 0; i < 8; i++) mu += red[i];
    mu *= (1.f / DD);

    float d = y - mu;
    float s2 = d * d;
#pragma unroll
    for (int off = 16; off; off >>= 1) s2 += __shfl_xor_sync(0xffffffffu, s2, off);
    __syncthreads();
    if (lane == 0) red[w] = s2;
    __syncthreads();
    float var = 0.f;
#pragma unroll
    for (int i = 0; i < 8; i++) var += red[i];
    var *= (1.f / DD);

    float z = d * rsqrtf(var + 1e-5f) * ln_g[t] + ln_b[t];
    float y2 = z / (1.f + __expf(-z));
    out[idx] = y2;
    splitbf(y2, g_h_hi[idx], g_h_lo[idx]);
}

// ---------------- launch ----------------
extern "C" void kernel_launch(void* const* d_in, const int* in_sizes, int n_in,
                              void* d_out, int out_size) {
    const float* x    = (const float*)d_in[0];
    const float* lu   = (const float*)d_in[1];
    const int*   ei   = (const int*)d_in[2];
    const float* t    = (const float*)d_in[3];
    const float* msg  = (const float*)d_in[4];
    const float* wlin = (const float*)d_in[5];
    const float* blin = (const float*)d_in[6];
    const float* w    = (const float*)d_in[7];
    const float* b    = (const float*)d_in[8];
    const float* lin_w = (const float*)d_in[9];
    const float* lin_b = (const float*)d_in[10];
    const float* Wq = (const float*)d_in[11];
    const float* bq = (const float*)d_in[12];
    const float* Wk = (const float*)d_in[13];
    const float* bk = (const float*)d_in[14];
    const float* Wv = (const float*)d_in[15];
    const float* bv = (const float*)d_in[16];
    const float* We = (const float*)d_in[17];
    const float* Ws = (const float*)d_in[18];
    const float* bs = (const float*)d_in[19];
    const float* lng = (const float*)d_in[20];
    const float* lnb = (const float*)d_in[21];
    float* out = (float*)d_out;

    cudaFuncSetAttribute(k_mma, cudaFuncAttributeMaxDynamicSharedMemorySize, SMEM_MM);

    void* p;
    cudaGetSymbolAddress(&p, g_h);    float* ph = (float*)p;
    cudaGetSymbolAddress(&p, g_q);    float* pq = (float*)p;
    cudaGetSymbolAddress(&p, g_k);    float* pk = (float*)p;
    cudaGetSymbolAddress(&p, g_v);    float* pv = (float*)p;
    cudaGetSymbolAddress(&p, g_skip); float* ps = (float*)p;
    cudaGetSymbolAddress(&p, g_z);    float* pz = (float*)p;
    cudaGetSymbolAddress(&p, g_ag2);  float* pg2 = (float*)p;
    cudaGetSymbolAddress(&p, g_bz);   float* pbz = (float*)p;
    cudaGetSymbolAddress(&p, g_h_hi);  __nv_bfloat16* hhi = (__nv_bfloat16*)p;
    cudaGetSymbolAddress(&p, g_h_lo);  __nv_bfloat16* hlo = (__nv_bfloat16*)p;
    cudaGetSymbolAddress(&p, g_x_hi);  __nv_bfloat16* xhi = (__nv_bfloat16*)p;
    cudaGetSymbolAddress(&p, g_x_lo);  __nv_bfloat16* xlo = (__nv_bfloat16*)p;
    cudaGetSymbolAddress(&p, g_wn_hi); __nv_bfloat16* wnh = (__nv_bfloat16*)p;
    cudaGetSymbolAddress(&p, g_wn_lo); __nv_bfloat16* wnl = (__nv_bfloat16*)p;
    cudaGetSymbolAddress(&p, g_we_hi); __nv_bfloat16* weh = (__nv_bfloat16*)p;
    cudaGetSymbolAddress(&p, g_we_lo); __nv_bfloat16* wel = (__nv_bfloat16*)p;
    cudaGetSymbolAddress(&p, g_wl_hi); __nv_bfloat16* wlh = (__nv_bfloat16*)p;
    cudaGetSymbolAddress(&p, g_wl_lo); __nv_bfloat16* wll = (__nv_bfloat16*)p;
    cudaGetSymbolAddress(&p, g_as_hi); __nv_bfloat16* ash = (__nv_bfloat16*)p;
    cudaGetSymbolAddress(&p, g_as_lo); __nv_bfloat16* asl = (__nv_bfloat16*)p;

    // CSR build + edge attrs + weight packing + composite z-weights
    k_zero_deg<<<(NN + 255) / 256, 256>>>();
    k_count<<<(EE + 255) / 256, 256>>>(ei);
    k_scan<<<1, 1024>>>();
    k_scatter<<<(EE + 255) / 256, 256>>>(ei);
    k_edge_attr<<<(EE * EK + 255) / 256, 256>>>(ei, lu, t, msg, wlin, blin, w, b);
    k_split_wn<<<(12 * 65536 + 255) / 256, 256>>>(Wq, Wk, Wv, Ws);
    k_wc<<<(3 * 65536 + 255) / 256, 256>>>(Wq, We);
    k_bz<<<3, 256>>>(bq, We);
    k_split_we<<<(3 * 256 * EK + 255) / 256, 256>>>(We);
    k_split_wl<<<(32768 + 255) / 256, 256>>>(lin_w);
    k_split_x<<<(NN * 128 + 255) / 256, 256>>>(x);

    dim3 gin(2, (NN + 127) / 128);
    dim3 gnode(10, (NN + 127) / 128);   // Q|K|V|S|Z fused, N=1280
    dim3 ges(1, (NN + 127) / 128);      // e-sum GEMM, N=128 per head

    k_mma<<<gin, 256, SMEM_MM>>>(xhi, xlo, wlh, wll,
                                 lin_b, lin_b, lin_b, lin_b, lin_b,
                                 ph, ph, ph, ph, ph, NN, 128);
    k_split_h<<<(NN * 256 + 255) / 256, 256>>>();

    for (int i = 0; i < LL; i++) {
        k_mma<<<gnode, 256, SMEM_MM>>>(hhi, hlo,
                                       wnh + i * 1280 * 256, wnl + i * 1280 * 256,
                                       bq + i * DD, bk + i * DD, bv + i * DD, bs + i * DD,
                                       pbz + i * 256,
                                       pq, pk, pv, ps, pz, NN, 256);
        k_attn<<<(NN * HH * 32 + 255) / 256, 256>>>();
        for (int h = 0; h < HH; h++) {
            k_mma<<<ges, 256, SMEM_MM>>>(ash + h * NN * EK, asl + h * NN * EK,
                                         weh + (i * 256 + h * 128) * EK,
                                         wel + (i * 256 + h * 128) * EK,
                                         (const float*)nullptr, nullptr, nullptr, nullptr, nullptr,
                                         pg2 + h * 128, nullptr, nullptr, nullptr, nullptr,
                                         NN, EK);
        }
        k_node_update<<<NN, DD>>>(lng + i * DD, lnb + i * DD, (i == LL - 1) ? out : ph);
    }
}